// round 2
// baseline (speedup 1.0000x reference)
#include <cuda_runtime.h>
#include <math.h>

#define NN 10000
#define NE 160000
#define ZZ 10
#define CC 64
#define NBS 8
#define NG 16
#define NSLOT 576
#define RMAXF 5.0f

__device__ float g_uhat[NE*3];
__device__ float g_len [NE];
__device__ float g_shv [NE*9];
__device__ float g_ef  [NE*8];
__device__ float g_def [NE*8];
__device__ float g_w0[NE*64];
__device__ float g_w1[NE*64];
__device__ float g_gw[NE*64];
__device__ float g_F0[NN*NSLOT];
__device__ float g_F1[NN*NSLOT];
__device__ float g_F2[NN*NSLOT];
__device__ float g_M0[NN*NSLOT];
__device__ float g_M1[NN*NSLOT];
__device__ float g_A [NN*NSLOT];
__device__ float g_T1[NN*NSLOT];
__device__ float g_G2[NN*NSLOT];
__device__ float g_G1[NN*NSLOT];
__device__ float g_gsh[NE*9];
__device__ float g_gef[NE*8];
__device__ float g_gpos[NN*3];
__device__ float g_adip[NN*3];
__device__ float g_eng[NG*3];
__device__ float g_tdb[NG*3];
__device__ int g_degr[NN], g_degs[NN];
__device__ int g_rowr[NN+1], g_rows[NN+1];
__device__ int g_curr[NN], g_curs[NN];
__device__ int g_eidr[NE], g_eids[NE];

__device__ __forceinline__ float* bufsel(int id){
  switch(id){
    case 0: return g_F0; case 1: return g_F1; case 2: return g_F2;
    case 3: return g_M0; case 4: return g_M1; case 5: return g_A;
    case 6: return g_T1; case 7: return g_G2; default: return g_G1;
  }
}

__global__ void k_zero(){
  int i = blockIdx.x*blockDim.x + threadIdx.x;
  if (i < NE*9) g_gsh[i] = 0.f;
  if (i < NE*8) g_gef[i] = 0.f;
  if (i < NN*3) { g_gpos[i] = 0.f; g_adip[i] = 0.f; }
  if (i < NG*3) { g_eng[i] = 0.f; g_tdb[i] = 0.f; }
  if (i < NN)   { g_degr[i] = 0; g_degs[i] = 0; }
}

__global__ void k_hist(const int* __restrict__ ei){
  int e = blockIdx.x*blockDim.x + threadIdx.x;
  if (e >= NE) return;
  atomicAdd(&g_degs[ei[e]], 1);
  atomicAdd(&g_degr[ei[NE+e]], 1);
}

__global__ void k_scan(){
  __shared__ int sh[1024];
  int t = threadIdx.x;
  for (int pass = 0; pass < 2; pass++){
    int* deg = pass ? g_degs : g_degr;
    int* row = pass ? g_rows : g_rowr;
    int* cur = pass ? g_curs : g_curr;
    int base = t*10;
    int s = 0;
    for (int j = 0; j < 10; j++){ int n = base+j; if (n < NN) s += deg[n]; }
    sh[t] = s; __syncthreads();
    for (int off = 1; off < 1024; off <<= 1){
      int v = (t >= off) ? sh[t-off] : 0;
      __syncthreads();
      sh[t] += v;
      __syncthreads();
    }
    int run = sh[t] - s;
    for (int j = 0; j < 10; j++){
      int n = base+j;
      if (n < NN){ row[n] = run; cur[n] = run; run += deg[n]; }
    }
    if (t == 1023) row[NN] = sh[1023];
    __syncthreads();
  }
}

__global__ void k_fill(const int* __restrict__ ei){
  int e = blockIdx.x*blockDim.x + threadIdx.x;
  if (e >= NE) return;
  int s = ei[e], r = ei[NE+e];
  int p = atomicAdd(&g_curs[s], 1); g_eids[p] = e;
  int q = atomicAdd(&g_curr[r], 1); g_eidr[q] = e;
}

__global__ void k_geom(const float* __restrict__ pos, const float* __restrict__ shifts,
                       const int* __restrict__ ei){
  int e = blockIdx.x*blockDim.x + threadIdx.x;
  if (e >= NE) return;
  int s = ei[e], r = ei[NE+e];
  float vx = pos[s*3+0] - pos[r*3+0] + shifts[e*3+0];
  float vy = pos[s*3+1] - pos[r*3+1] + shifts[e*3+1];
  float vz = pos[s*3+2] - pos[r*3+2] + shifts[e*3+2];
  float len = sqrtf(vx*vx + vy*vy + vz*vz + 1e-12f);
  float inv = 1.f/len;
  float x = vx*inv, y = vy*inv, z = vz*inv;
  g_uhat[e*3+0] = x; g_uhat[e*3+1] = y; g_uhat[e*3+2] = z;
  g_len[e] = len;
  const float s3 = 1.7320508075688772f, s5 = 2.23606797749979f, s15 = 3.872983346207417f;
  g_shv[e*9+0] = 1.f;
  g_shv[e*9+1] = s3*x;  g_shv[e*9+2] = s3*y;  g_shv[e*9+3] = s3*z;
  g_shv[e*9+4] = s15*x*y; g_shv[e*9+5] = s15*y*z;
  g_shv[e*9+6] = 0.5f*s5*(3.f*z*z - 1.f);
  g_shv[e*9+7] = s15*x*z; g_shv[e*9+8] = 0.5f*s15*(x*x - y*y);
  float u = len / RMAXF;
  float fc = 0.f, dfc = 0.f;
  if (u < 1.f){
    float u2 = u*u, u4 = u2*u2, u5 = u4*u, u6 = u5*u, u7 = u6*u;
    fc  = 1.f - 21.f*u5 + 35.f*u6 - 15.f*u7;
    dfc = (-105.f*u4 + 210.f*u5 - 105.f*u6) / RMAXF;
  }
  float ire = 1.f/(len + 1e-9f);
  float amp = 0.6324555320336759f;
  #pragma unroll
  for (int b = 0; b < NBS; b++){
    float kb = (float)(b+1) * 3.14159265358979323846f / RMAXF;
    float sarg, carg;
    sincosf(kb*len, &sarg, &carg);
    float bess  = amp * sarg * ire;
    float dbess = amp * (kb*carg*ire - sarg*ire*ire);
    g_ef [e*8+b] = bess*fc;
    g_def[e*8+b] = dbess*fc + bess*dfc;
  }
}

__global__ void k_embed(const float* __restrict__ attrs, const float* __restrict__ Wemb,
                        const float* __restrict__ ae, const int* __restrict__ batch){
  int i = blockIdx.x*blockDim.x + threadIdx.x;
  if (i >= NN*64) return;
  int n = i >> 6, c = i & 63;
  float acc = 0.f;
  #pragma unroll
  for (int zq = 0; zq < ZZ; zq++) acc += attrs[n*ZZ+zq]*Wemb[zq*CC+c];
  g_F0[n*NSLOT + c] = acc;
  #pragma unroll
  for (int k = 1; k < 9; k++) g_F0[n*NSLOT + k*64 + c] = 0.f;
  if (c == 0){
    float e0 = 0.f;
    #pragma unroll
    for (int zq = 0; zq < ZZ; zq++) e0 += attrs[n*ZZ+zq]*ae[zq];
    atomicAdd(&g_eng[batch[n]*3 + 0], e0);
  }
}

__global__ void k_edge_mlp(const float* __restrict__ W1, const float* __restrict__ W2, int t){
  __shared__ float W1s[8*64];
  __shared__ float W2s[64*65];
  __shared__ float efs[4][8];
  __shared__ float as_[4][64];
  float* wout = t ? g_w1 : g_w0;
  int tid = threadIdx.x;
  for (int i = tid; i < 512; i += 256) W1s[i] = W1[i];
  for (int i = tid; i < 4096; i += 256) W2s[(i>>6)*65 + (i&63)] = W2[i];
  __syncthreads();
  int sub = tid >> 6, j = tid & 63;
  for (int g = 0; g < 8; g++){
    int ebase = blockIdx.x*32 + g*4;
    if (tid < 32) efs[tid>>3][tid&7] = g_ef[(ebase + (tid>>3))*8 + (tid&7)];
    __syncthreads();
    float z = 0.f;
    #pragma unroll
    for (int b = 0; b < 8; b++) z += efs[sub][b]*W1s[b*64 + j];
    float sig = 1.f/(1.f + expf(-z));
    as_[sub][j] = z*sig;
    __syncthreads();
    float acc = 0.f;
    #pragma unroll
    for (int jj = 0; jj < 64; jj++) acc += as_[sub][jj]*W2s[jj*65 + j];
    wout[(ebase+sub)*64 + j] = acc;
    __syncthreads();
  }
}

__global__ void k_agg(int t, const int* __restrict__ ei){
  int n = blockIdx.x, c = threadIdx.x;
  const float* Fin  = t ? g_F1 : g_F0;
  const float* warr = t ? g_w1 : g_w0;
  float acc[9] = {0,0,0,0,0,0,0,0,0};
  int i1 = g_rowr[n+1];
  for (int i = g_rowr[n]; i < i1; i++){
    int e = g_eidr[i];
    int s = ei[e];
    float x = Fin[s*NSLOT + c] * warr[e*64 + c];
    #pragma unroll
    for (int k = 0; k < 9; k++) acc[k] += x * __ldg(&g_shv[e*9 + k]);
  }
  #pragma unroll
  for (int k = 0; k < 9; k++) g_A[n*NSLOT + k*64 + c] = acc[k] * 0.0625f;
}

template<bool TR, bool ACC>
__global__ void k_pll(int in_id, int out_id, const float* __restrict__ Wb){
  int l = blockIdx.y;
  int nk = (l == 0) ? 1 : ((l == 1) ? 3 : 5);
  int ks = (l == 0) ? 0 : ((l == 1) ? 1 : 4);
  int rows = NN*nk;
  int rb = blockIdx.x*64;
  if (rb >= rows) return;
  const float* in  = bufsel(in_id);
  float* out = bufsel(out_id);
  const float* W = Wb + l*4096;
  __shared__ float As[64][65];
  __shared__ float Ws[64][65];
  int tid = threadIdx.x;
  #pragma unroll
  for (int ii = 0; ii < 16; ii++){
    int idx = ii*256 + tid;
    int rr = idx >> 6, col = idx & 63;
    int rg = rb + rr;
    float v = 0.f;
    if (rg < rows){
      int n = rg / nk; int k = ks + rg % nk;
      v = in[(n*9 + k)*64 + col];
    }
    As[rr][col] = v;
    Ws[rr][col] = W[idx];
  }
  __syncthreads();
  int tx = tid & 15, ty = tid >> 4;
  float acc[4][4] = {};
  #pragma unroll
  for (int kk = 0; kk < 64; kk++){
    float a[4], b[4];
    #pragma unroll
    for (int i = 0; i < 4; i++) a[i] = As[ty*4+i][kk];
    #pragma unroll
    for (int j = 0; j < 4; j++) b[j] = TR ? Ws[tx*4+j][kk] : Ws[kk][tx*4+j];
    #pragma unroll
    for (int i = 0; i < 4; i++)
      #pragma unroll
      for (int j = 0; j < 4; j++) acc[i][j] += a[i]*b[j];
  }
  #pragma unroll
  for (int i = 0; i < 4; i++){
    int rg = rb + ty*4 + i;
    if (rg >= rows) continue;
    int n = rg / nk; int k = ks + rg % nk;
    int base = (n*9 + k)*64 + tx*4;
    #pragma unroll
    for (int j = 0; j < 4; j++){
      if (ACC) out[base+j] += acc[i][j];
      else     out[base+j]  = acc[i][j];
    }
  }
}

__global__ void k_mp(int t, const float* __restrict__ wp){
  int i = blockIdx.x*blockDim.x + threadIdx.x;
  if (i >= NN*64) return;
  int n = i >> 6, c = i & 63;
  const float* M = t ? g_M1 : g_M0;
  float s0 = M[n*NSLOT + c];
  float P = wp[c*3+0] + wp[c*3+1]*s0 + wp[c*3+2]*s0*s0;
  #pragma unroll
  for (int k = 0; k < 9; k++) g_T1[n*NSLOT + k*64 + c] = M[n*NSLOT + k*64 + c] * P;
}

__device__ __forceinline__ float blk64_reduce(float v, float* sred, int c){
  sred[c] = v; __syncthreads();
  if (c < 32) sred[c] += sred[c+32];
  __syncthreads();
  float r = 0.f;
  if (c < 32){
    r = sred[c];
    #pragma unroll
    for (int o = 16; o > 0; o >>= 1) r += __shfl_down_sync(0xffffffffu, r, o);
  }
  __syncthreads();
  return r;
}

__global__ void k_ed(int t, const float* __restrict__ we, const float* __restrict__ wd,
                     const int* __restrict__ batch){
  __shared__ float sred[64];
  int n = blockIdx.x, c = threadIdx.x;
  const float* Fn = t ? g_F2 : g_F1;
  float se = blk64_reduce(Fn[n*NSLOT + c]*we[c], sred, c);
  if (c == 0) atomicAdd(&g_eng[batch[n]*3 + 1 + t], se);
  #pragma unroll
  for (int m = 0; m < 3; m++){
    float sd = blk64_reduce(Fn[n*NSLOT + (1+m)*64 + c]*wd[c], sred, c);
    if (c == 0) g_adip[n*3+m] += sd;
  }
}

__global__ void k_setG2(const float* __restrict__ we1){
  int i = blockIdx.x*blockDim.x + threadIdx.x;
  if (i >= NN*NSLOT) return;
  int rem = i % NSLOT; int k = rem >> 6; int c = rem & 63;
  g_G2[i] = (k == 0) ? we1[c] : 0.f;
}

__global__ void k_addwe(const float* __restrict__ we0){
  int i = blockIdx.x*blockDim.x + threadIdx.x;
  if (i >= NN*64) return;
  int n = i >> 6, c = i & 63;
  g_G1[n*NSLOT + c] += we0[c];
}

__global__ void k_polyback(int t, const float* __restrict__ wp){
  int i = blockIdx.x*blockDim.x + threadIdx.x;
  if (i >= NN*64) return;
  int n = i >> 6, c = i & 63;
  const float* M = t ? g_M1 : g_M0;
  float m[9], g[9];
  #pragma unroll
  for (int k = 0; k < 9; k++){
    m[k] = M[n*NSLOT + k*64 + c];
    g[k] = g_T1[n*NSLOT + k*64 + c];
  }
  float s0 = m[0];
  float P  = wp[c*3+0] + wp[c*3+1]*s0 + wp[c*3+2]*s0*s0;
  float dP = wp[c*3+1] + 2.f*wp[c*3+2]*s0;
  float dot = 0.f;
  #pragma unroll
  for (int k = 0; k < 9; k++) dot += g[k]*m[k];
  #pragma unroll
  for (int k = 0; k < 9; k++){
    float o = g[k]*P;
    if (k == 0) o += dot*dP;
    g_T1[n*NSLOT + k*64 + c] = o;
  }
}

__global__ void k_edge_bwd(int t, int writeG, const int* __restrict__ ei){
  __shared__ float pr[2][9];
  int s = blockIdx.x, c = threadIdx.x;
  const float* Fin  = t ? g_F1 : g_F0;
  const float* warr = t ? g_w1 : g_w0;
  float h = Fin[s*NSLOT + c];
  float acc = 0.f;
  int i1 = g_rows[s+1];
  int warp = c >> 5, lane = c & 31;
  for (int i = g_rows[s]; i < i1; i++){
    int e = g_eids[i];
    int r = ei[NE + e];
    float gm[9], shv[9];
    #pragma unroll
    for (int k = 0; k < 9; k++){
      gm[k] = g_A[r*NSLOT + k*64 + c] * 0.0625f;
      shv[k] = __ldg(&g_shv[e*9 + k]);
    }
    float t1 = 0.f;
    #pragma unroll
    for (int k = 0; k < 9; k++) t1 += gm[k]*shv[k];
    float wv = warr[e*64 + c];
    g_gw[e*64 + c] = h*t1;
    acc += wv*t1;
    float y = wv*h;
    float v[9];
    #pragma unroll
    for (int k = 0; k < 9; k++) v[k] = gm[k]*y;
    #pragma unroll
    for (int o = 16; o > 0; o >>= 1)
      #pragma unroll
      for (int k = 0; k < 9; k++) v[k] += __shfl_down_sync(0xffffffffu, v[k], o);
    if (lane == 0)
      #pragma unroll
      for (int k = 0; k < 9; k++) pr[warp][k] = v[k];
    __syncthreads();
    if (c < 9) g_gsh[e*9 + c] += pr[0][c] + pr[1][c];
    __syncthreads();
  }
  if (writeG) g_G1[s*NSLOT + c] += acc;
}

__global__ void k_mlp_bwd(const float* __restrict__ W1, const float* __restrict__ W2){
  __shared__ float W1s[8*64];
  __shared__ float W2s[64*65];
  __shared__ float efs[4][8];
  __shared__ float gws[4][64];
  __shared__ float gzs[4][64];
  __shared__ float part[4][8][8];
  int tid = threadIdx.x;
  for (int i = tid; i < 512; i += 256) W1s[i] = W1[i];
  for (int i = tid; i < 4096; i += 256) W2s[(i>>6)*65 + (i&63)] = W2[i];
  __syncthreads();
  int sub = tid >> 6, j = tid & 63;
  for (int g = 0; g < 8; g++){
    int ebase = blockIdx.x*32 + g*4;
    int e = ebase + sub;
    if (tid < 32) efs[tid>>3][tid&7] = g_ef[(ebase + (tid>>3))*8 + (tid&7)];
    gws[sub][j] = g_gw[e*64 + j];
    __syncthreads();
    float ga = 0.f;
    #pragma unroll
    for (int cc = 0; cc < 64; cc++) ga += gws[sub][cc]*W2s[j*65 + cc];
    float z = 0.f;
    #pragma unroll
    for (int b = 0; b < 8; b++) z += efs[sub][b]*W1s[b*64 + j];
    float sig = 1.f/(1.f + expf(-z));
    gzs[sub][j] = ga*sig*(1.f + z*(1.f - sig));
    __syncthreads();
    {
      int seg = (tid & 63) >> 3, b = tid & 7;
      float p = 0.f;
      #pragma unroll
      for (int q = 0; q < 8; q++) p += gzs[sub][seg*8 + q]*W1s[b*64 + seg*8 + q];
      part[sub][b][seg] = p;
    }
    __syncthreads();
    if (tid < 32){
      int su = tid >> 3, b = tid & 7;
      float sum = 0.f;
      #pragma unroll
      for (int q = 0; q < 8; q++) sum += part[su][b][q];
      g_gef[(ebase + su)*8 + b] += sum;
    }
    __syncthreads();
  }
}

__global__ void k_geom_bwd(const int* __restrict__ ei){
  int e = blockIdx.x*blockDim.x + threadIdx.x;
  if (e >= NE) return;
  float gl = 0.f;
  #pragma unroll
  for (int b = 0; b < 8; b++) gl += g_gef[e*8+b]*g_def[e*8+b];
  float g1 = g_gsh[e*9+1], g2 = g_gsh[e*9+2], g3 = g_gsh[e*9+3];
  float g4 = g_gsh[e*9+4], g5 = g_gsh[e*9+5], g6 = g_gsh[e*9+6];
  float g7 = g_gsh[e*9+7], g8 = g_gsh[e*9+8];
  float x = g_uhat[e*3+0], y = g_uhat[e*3+1], z = g_uhat[e*3+2];
  const float s3 = 1.7320508075688772f, s5 = 2.23606797749979f, s15 = 3.872983346207417f;
  float gux = s3*g1 + s15*(y*g4 + z*g7 + x*g8);
  float guy = s3*g2 + s15*(x*g4 + z*g5 - y*g8);
  float guz = s3*g3 + s15*(y*g5 + x*g7) + 3.f*s5*z*g6;
  float len = g_len[e];
  float gdu = gux*x + guy*y + guz*z;
  float inv = 1.f/len;
  float gvx = x*gl + (gux - x*gdu)*inv;
  float gvy = y*gl + (guy - y*gdu)*inv;
  float gvz = z*gl + (guz - z*gdu)*inv;
  int s = ei[e], r = ei[NE+e];
  atomicAdd(&g_gpos[s*3+0],  gvx);
  atomicAdd(&g_gpos[s*3+1],  gvy);
  atomicAdd(&g_gpos[s*3+2],  gvz);
  atomicAdd(&g_gpos[r*3+0], -gvx);
  atomicAdd(&g_gpos[r*3+1], -gvy);
  atomicAdd(&g_gpos[r*3+2], -gvz);
}

__global__ void k_asm_node(float* __restrict__ out, const float* __restrict__ charges,
                           const float* __restrict__ pos, const int* __restrict__ batch){
  int n = blockIdx.x*blockDim.x + threadIdx.x;
  if (n >= NN) return;
  int g = batch[n];
  float q = charges[n];
  #pragma unroll
  for (int i = 0; i < 3; i++){
    out[64 + n*3 + i] = -g_gpos[n*3+i];
    float a = g_adip[n*3+i];
    out[30112 + n*3 + i] = a;
    atomicAdd(&g_tdb[g*3+i], a + q*pos[n*3+i]);
  }
}

__global__ void k_asm_graph(float* __restrict__ out){
  int g = threadIdx.x;
  if (g >= NG) return;
  float c0 = g_eng[g*3+0], c1 = g_eng[g*3+1], c2 = g_eng[g*3+2];
  out[g] = c0 + c1 + c2;
  out[16 + g*3 + 0] = c0;
  out[16 + g*3 + 1] = c1;
  out[16 + g*3 + 2] = c2;
  #pragma unroll
  for (int i = 0; i < 3; i++) out[30064 + g*3 + i] = g_tdb[g*3+i];
}

extern "C" void kernel_launch(void* const* d_in, const int* in_sizes, int n_in,
                              void* d_out, int out_size){
  const float* pos    = (const float*)d_in[0];
  const float* attrs  = (const float*)d_in[1];
  const float* chg    = (const float*)d_in[2];
  const float* shifts = (const float*)d_in[3];
  const float* Wemb   = (const float*)d_in[4];
  const float* ae     = (const float*)d_in[5];
  const float* Wr1    = (const float*)d_in[6];
  const float* Wr2    = (const float*)d_in[7];
  const float* Wmix   = (const float*)d_in[8];
  const float* Wsc    = (const float*)d_in[9];
  const float* wpoly  = (const float*)d_in[10];
  const float* Wprod  = (const float*)d_in[11];
  const float* w_e    = (const float*)d_in[12];
  const float* w_d    = (const float*)d_in[13];
  const int*   ei     = (const int*)d_in[14];
  const int*   batch  = (const int*)d_in[15];
  float* out = (float*)d_out;

  dim3 gg((NN*5 + 63)/64, 3);

  k_zero<<<(NE*9 + 255)/256, 256>>>();
  k_hist<<<NE/256, 256>>>(ei);
  k_scan<<<1, 1024>>>();
  k_fill<<<NE/256, 256>>>(ei);
  k_geom<<<NE/256, 256>>>(pos, shifts, ei);
  k_embed<<<(NN*64)/256, 256>>>(attrs, Wemb, ae, batch);

  // forward t=0
  k_edge_mlp<<<NE/32, 256>>>(Wr1, Wr2, 0);
  k_agg<<<NN, 64>>>(0, ei);
  k_pll<false,false><<<gg, 256>>>(5, 3, Wmix);           // M0 = A @ Wmix0
  k_mp<<<(NN*64)/256, 256>>>(0, wpoly);                  // T1 = M0 * P
  k_pll<false,false><<<gg, 256>>>(6, 1, Wprod);          // F1 = T1 @ Wprod0
  k_pll<false,true ><<<gg, 256>>>(0, 1, Wsc);            // F1 += F0 @ Wsc0
  k_ed<<<NN, 64>>>(0, w_e, w_d, batch);

  // forward t=1
  k_edge_mlp<<<NE/32, 256>>>(Wr1 + 512, Wr2 + 4096, 1);
  k_agg<<<NN, 64>>>(1, ei);
  k_pll<false,false><<<gg, 256>>>(5, 4, Wmix + 12288);   // M1
  k_mp<<<(NN*64)/256, 256>>>(1, wpoly + 192);
  k_pll<false,false><<<gg, 256>>>(6, 2, Wprod + 12288);  // F2
  k_pll<false,true ><<<gg, 256>>>(1, 2, Wsc + 12288);
  k_ed<<<NN, 64>>>(1, w_e + 64, w_d + 64, batch);

  // backward layer 1
  k_setG2<<<(NN*NSLOT)/256, 256>>>(w_e + 64);
  k_pll<true,false><<<gg, 256>>>(7, 6, Wprod + 12288);   // G_T1
  k_pll<true,false><<<gg, 256>>>(7, 8, Wsc + 12288);     // G_F1
  k_polyback<<<(NN*64)/256, 256>>>(1, wpoly + 192);      // G_T1 -> G_M1
  k_pll<true,false><<<gg, 256>>>(6, 5, Wmix + 12288);    // G_A1
  k_edge_bwd<<<NN, 64>>>(1, 1, ei);
  k_mlp_bwd<<<NE/32, 256>>>(Wr1 + 512, Wr2 + 4096);
  k_addwe<<<(NN*64)/256, 256>>>(w_e);

  // backward layer 0 (no grad needed into F0)
  k_pll<true,false><<<gg, 256>>>(8, 6, Wprod);           // G_T1
  k_polyback<<<(NN*64)/256, 256>>>(0, wpoly);            // G_T1 -> G_M0
  k_pll<true,false><<<gg, 256>>>(6, 5, Wmix);            // G_A0
  k_edge_bwd<<<NN, 64>>>(0, 0, ei);
  k_mlp_bwd<<<NE/32, 256>>>(Wr1, Wr2);

  k_geom_bwd<<<NE/256, 256>>>(ei);
  k_asm_node<<<(NN + 255)/256, 256>>>(out, chg, pos, batch);
  k_asm_graph<<<1, 32>>>(out);
}

// round 3
// speedup vs baseline: 1.2049x; 1.2049x over previous
#include <cuda_runtime.h>
#include <math.h>
#include <stdint.h>

#define NN 10000
#define NE 160000
#define ZZ 10
#define CC 64
#define NBS 8
#define NG 16
#define NSLOT 576
#define RMAXF 5.0f

typedef unsigned long long u64;

__device__ float g_uhat[NE*3];
__device__ float g_len [NE];
__device__ float g_shv [NE*9];
__device__ float g_ef  [NE*8];
__device__ float g_def [NE*8];
__device__ float g_w0[NE*64];
__device__ float g_w1[NE*64];
__device__ float g_gw[NE*64];
__device__ float g_act[NE*64];
__device__ float g_te [NE*64];
__device__ float g_F0[NN*NSLOT];
__device__ float g_F1[NN*NSLOT];
__device__ float g_F2[NN*NSLOT];
__device__ float g_M0[NN*NSLOT];
__device__ float g_M1[NN*NSLOT];
__device__ float g_A [NN*NSLOT];
__device__ float g_T1[NN*NSLOT];
__device__ float g_G2[NN*NSLOT];
__device__ float g_G1[NN*NSLOT];
__device__ float g_gsh[NE*9];
__device__ float g_gef[NE*8];
__device__ float g_gpos[NN*3];
__device__ float g_adip[NN*3];
__device__ float g_eng[NG*3];
__device__ float g_tdb[NG*3];
__device__ int g_degr[NN], g_degs[NN];
__device__ int g_rowr[NN+1], g_rows[NN+1];
__device__ int g_curr[NN], g_curs[NN];
__device__ int g_eidr[NE], g_eids[NE];

__device__ __forceinline__ float* bufsel(int id){
  switch(id){
    case 0: return g_F0; case 1: return g_F1; case 2: return g_F2;
    case 3: return g_M0; case 4: return g_M1; case 5: return g_A;
    case 6: return g_T1; case 7: return g_G2; case 8: return g_G1;
    case 9: return g_act; case 10: return g_w0; case 11: return g_w1;
    case 12: return g_gw; default: return g_te;
  }
}

__device__ __forceinline__ u64 dupf(unsigned x){
  u64 r; asm("mov.b64 %0,{%1,%1};" : "=l"(r) : "r"(x)); return r;
}
__device__ __forceinline__ void fma2(u64 &c, u64 a, u64 b){
  asm("fma.rn.f32x2 %0,%1,%2,%3;" : "=l"(c) : "l"(a), "l"(b), "l"(c));
}
__device__ __forceinline__ float2 asf2(u64 v){
  float2 f;
  f.x = __uint_as_float((unsigned)v);
  f.y = __uint_as_float((unsigned)(v >> 32));
  return f;
}

__global__ void k_zero(){
  int i = blockIdx.x*blockDim.x + threadIdx.x;
  if (i < NE*9) g_gsh[i] = 0.f;
  if (i < NE*8) g_gef[i] = 0.f;
  if (i < NN*3) { g_gpos[i] = 0.f; g_adip[i] = 0.f; }
  if (i < NG*3) { g_eng[i] = 0.f; g_tdb[i] = 0.f; }
  if (i < NN)   { g_degr[i] = 0; g_degs[i] = 0; }
}

__global__ void k_hist(const int* __restrict__ ei){
  int e = blockIdx.x*blockDim.x + threadIdx.x;
  if (e >= NE) return;
  atomicAdd(&g_degs[ei[e]], 1);
  atomicAdd(&g_degr[ei[NE+e]], 1);
}

__global__ void k_scan(){
  __shared__ int sh[1024];
  int t = threadIdx.x;
  for (int pass = 0; pass < 2; pass++){
    int* deg = pass ? g_degs : g_degr;
    int* row = pass ? g_rows : g_rowr;
    int* cur = pass ? g_curs : g_curr;
    int base = t*10;
    int s = 0;
    for (int j = 0; j < 10; j++){ int n = base+j; if (n < NN) s += deg[n]; }
    sh[t] = s; __syncthreads();
    for (int off = 1; off < 1024; off <<= 1){
      int v = (t >= off) ? sh[t-off] : 0;
      __syncthreads();
      sh[t] += v;
      __syncthreads();
    }
    int run = sh[t] - s;
    for (int j = 0; j < 10; j++){
      int n = base+j;
      if (n < NN){ row[n] = run; cur[n] = run; run += deg[n]; }
    }
    if (t == 1023) row[NN] = sh[1023];
    __syncthreads();
  }
}

__global__ void k_fill(const int* __restrict__ ei){
  int e = blockIdx.x*blockDim.x + threadIdx.x;
  if (e >= NE) return;
  int s = ei[e], r = ei[NE+e];
  int p = atomicAdd(&g_curs[s], 1); g_eids[p] = e;
  int q = atomicAdd(&g_curr[r], 1); g_eidr[q] = e;
}

__global__ void k_geom(const float* __restrict__ pos, const float* __restrict__ shifts,
                       const int* __restrict__ ei){
  int e = blockIdx.x*blockDim.x + threadIdx.x;
  if (e >= NE) return;
  int s = ei[e], r = ei[NE+e];
  float vx = pos[s*3+0] - pos[r*3+0] + shifts[e*3+0];
  float vy = pos[s*3+1] - pos[r*3+1] + shifts[e*3+1];
  float vz = pos[s*3+2] - pos[r*3+2] + shifts[e*3+2];
  float len = sqrtf(vx*vx + vy*vy + vz*vz + 1e-12f);
  float inv = 1.f/len;
  float x = vx*inv, y = vy*inv, z = vz*inv;
  g_uhat[e*3+0] = x; g_uhat[e*3+1] = y; g_uhat[e*3+2] = z;
  g_len[e] = len;
  const float s3 = 1.7320508075688772f, s5 = 2.23606797749979f, s15 = 3.872983346207417f;
  g_shv[e*9+0] = 1.f;
  g_shv[e*9+1] = s3*x;  g_shv[e*9+2] = s3*y;  g_shv[e*9+3] = s3*z;
  g_shv[e*9+4] = s15*x*y; g_shv[e*9+5] = s15*y*z;
  g_shv[e*9+6] = 0.5f*s5*(3.f*z*z - 1.f);
  g_shv[e*9+7] = s15*x*z; g_shv[e*9+8] = 0.5f*s15*(x*x - y*y);
  float u = len / RMAXF;
  float fc = 0.f, dfc = 0.f;
  if (u < 1.f){
    float u2 = u*u, u4 = u2*u2, u5 = u4*u, u6 = u5*u, u7 = u6*u;
    fc  = 1.f - 21.f*u5 + 35.f*u6 - 15.f*u7;
    dfc = (-105.f*u4 + 210.f*u5 - 105.f*u6) / RMAXF;
  }
  float ire = 1.f/(len + 1e-9f);
  float amp = 0.6324555320336759f;
  #pragma unroll
  for (int b = 0; b < NBS; b++){
    float kb = (float)(b+1) * 3.14159265358979323846f / RMAXF;
    float sarg, carg;
    sincosf(kb*len, &sarg, &carg);
    float bess  = amp * sarg * ire;
    float dbess = amp * (kb*carg*ire - sarg*ire*ire);
    g_ef [e*8+b] = bess*fc;
    g_def[e*8+b] = dbess*fc + bess*dfc;
  }
}

__global__ void k_embed(const float* __restrict__ attrs, const float* __restrict__ Wemb,
                        const float* __restrict__ ae, const int* __restrict__ batch){
  int i = blockIdx.x*blockDim.x + threadIdx.x;
  if (i >= NN*64) return;
  int n = i >> 6, c = i & 63;
  float acc = 0.f;
  #pragma unroll
  for (int zq = 0; zq < ZZ; zq++) acc += attrs[n*ZZ+zq]*Wemb[zq*CC+c];
  g_F0[n*NSLOT + c] = acc;
  #pragma unroll
  for (int k = 1; k < 9; k++) g_F0[n*NSLOT + k*64 + c] = 0.f;
  if (c == 0){
    float e0 = 0.f;
    #pragma unroll
    for (int zq = 0; zq < ZZ; zq++) e0 += attrs[n*ZZ+zq]*ae[zq];
    atomicAdd(&g_eng[batch[n]*3 + 0], e0);
  }
}

// silu(ef @ W1) -> g_act
__global__ void k_mlp1(const float* __restrict__ W1){
  __shared__ float W1s[512];
  __shared__ float efs[4][8];
  int tid = threadIdx.x;
  for (int i = tid; i < 512; i += 256) W1s[i] = W1[i];
  int ebase = blockIdx.x*4;
  if (tid < 32) efs[tid>>3][tid&7] = g_ef[(ebase + (tid>>3))*8 + (tid&7)];
  __syncthreads();
  int sub = tid >> 6, j = tid & 63;
  float z = 0.f;
  #pragma unroll
  for (int b = 0; b < 8; b++) z += efs[sub][b]*W1s[b*64 + j];
  float sig = 1.f/(1.f + expf(-z));
  g_act[(ebase+sub)*64 + j] = z*sig;
}

// general tiled GEMM with packed f32x2 FMA.
// out = in @ Weff where Weff = W (TR=false) or W^T (TR=true)
// DIN: out1 = in1@W1 + in2@W2.  DOUT: out1 = in1@W1eff, out2 = in1@W2eff.
template<bool TR, bool DIN, bool DOUT, bool FLAT>
__global__ void k_gemm(int in1_id, int in2_id, int out1_id, int out2_id,
                       const float* __restrict__ W1b, const float* __restrict__ W2b){
  int l  = FLAT ? 0 : blockIdx.y;
  int nk = FLAT ? 1 : ((l == 0) ? 1 : ((l == 1) ? 3 : 5));
  int ks = FLAT ? 0 : ((l == 0) ? 0 : ((l == 1) ? 1 : 4));
  int rows = FLAT ? NE : NN*nk;
  int rb = blockIdx.x*64;
  if (rb >= rows) return;
  const float* Wp1 = FLAT ? W1b : (W1b + l*4096);
  const float* Wp2 = (DIN || DOUT) ? (FLAT ? W2b : (W2b + l*4096)) : (const float*)0;
  __shared__ __align__(16) float As[64][66];
  __shared__ __align__(16) float Ws[64][66];
  int tid = threadIdx.x;
  int tx = tid & 15, ty = tid >> 4;
  u64 acc[2][4] = {};
  const int NP = (DIN || DOUT) ? 2 : 1;
  #pragma unroll
  for (int p = 0; p < NP; p++){
    const float* in = bufsel((DIN && p == 1) ? in2_id : in1_id);
    const float* W  = (p == 0) ? Wp1 : Wp2;
    #pragma unroll
    for (int ii = 0; ii < 16; ii++){
      int idx = ii*256 + tid;
      int rr = idx >> 6, cc = idx & 63;
      if (!(DOUT && p == 1)){
        int rg = rb + rr;
        float v = 0.f;
        if (rg < rows){
          int adr;
          if (FLAT) adr = rg*64 + cc;
          else { int n = rg/nk; int k = ks + rg%nk; adr = (n*9 + k)*64 + cc; }
          v = in[adr];
        }
        As[cc][rr] = v;
      }
      if (TR) Ws[cc][rr] = W[idx];
      else    Ws[rr][cc] = W[idx];
    }
    __syncthreads();
    #pragma unroll 4
    for (int kk = 0; kk < 64; kk++){
      const u64* ap = (const u64*)&As[kk][ty*4];
      const u64* bp = (const u64*)&Ws[kk][tx*4];
      u64 a01 = ap[0], a23 = ap[1];
      u64 b01 = bp[0], b23 = bp[1];
      u64 B0 = dupf((unsigned)b01), B1 = dupf((unsigned)(b01 >> 32));
      u64 B2 = dupf((unsigned)b23), B3 = dupf((unsigned)(b23 >> 32));
      fma2(acc[0][0], a01, B0); fma2(acc[0][1], a01, B1);
      fma2(acc[0][2], a01, B2); fma2(acc[0][3], a01, B3);
      fma2(acc[1][0], a23, B0); fma2(acc[1][1], a23, B1);
      fma2(acc[1][2], a23, B2); fma2(acc[1][3], a23, B3);
    }
    __syncthreads();
    if (DOUT || p == NP-1){
      float* out = bufsel(DOUT ? ((p == 0) ? out1_id : out2_id) : out1_id);
      #pragma unroll
      for (int i2 = 0; i2 < 2; i2++){
        float2 c0 = asf2(acc[i2][0]), c1 = asf2(acc[i2][1]);
        float2 c2 = asf2(acc[i2][2]), c3 = asf2(acc[i2][3]);
        #pragma unroll
        for (int h = 0; h < 2; h++){
          int rg = rb + ty*4 + i2*2 + h;
          if (rg >= rows) continue;
          int adr;
          if (FLAT) adr = rg*64 + tx*4;
          else { int n = rg/nk; int k = ks + rg%nk; adr = (n*9 + k)*64 + tx*4; }
          float4 v = h ? make_float4(c0.y, c1.y, c2.y, c3.y)
                       : make_float4(c0.x, c1.x, c2.x, c3.x);
          *(float4*)&out[adr] = v;
        }
      }
      if (DOUT){
        #pragma unroll
        for (int i2 = 0; i2 < 2; i2++)
          #pragma unroll
          for (int j = 0; j < 4; j++) acc[i2][j] = 0ull;
      }
    }
  }
}

__global__ void k_agg(int t, const int* __restrict__ ei){
  int node = blockIdx.x*4 + (threadIdx.x >> 6);
  int c = threadIdx.x & 63;
  if (node >= NN) return;
  const float* Fin  = t ? g_F1 : g_F0;
  const float* warr = t ? g_w1 : g_w0;
  float acc[9] = {0,0,0,0,0,0,0,0,0};
  int i1 = g_rowr[node+1];
  for (int i = g_rowr[node]; i < i1; i++){
    int e = g_eidr[i];
    int s = ei[e];
    float x = Fin[s*NSLOT + c] * warr[e*64 + c];
    #pragma unroll
    for (int k = 0; k < 9; k++) acc[k] += x * __ldg(&g_shv[e*9 + k]);
  }
  #pragma unroll
  for (int k = 0; k < 9; k++) g_A[node*NSLOT + k*64 + c] = acc[k] * 0.0625f;
}

__global__ void k_mp(int t, const float* __restrict__ wp){
  int i = blockIdx.x*blockDim.x + threadIdx.x;
  if (i >= NN*64) return;
  int n = i >> 6, c = i & 63;
  const float* M = t ? g_M1 : g_M0;
  float s0 = M[n*NSLOT + c];
  float P = wp[c*3+0] + wp[c*3+1]*s0 + wp[c*3+2]*s0*s0;
  #pragma unroll
  for (int k = 0; k < 9; k++) g_T1[n*NSLOT + k*64 + c] = M[n*NSLOT + k*64 + c] * P;
}

__device__ __forceinline__ float blk64_reduce(float v, float* sred, int c){
  sred[c] = v; __syncthreads();
  if (c < 32) sred[c] += sred[c+32];
  __syncthreads();
  float r = 0.f;
  if (c < 32){
    r = sred[c];
    #pragma unroll
    for (int o = 16; o > 0; o >>= 1) r += __shfl_down_sync(0xffffffffu, r, o);
  }
  __syncthreads();
  return r;
}

__global__ void k_ed(int t, const float* __restrict__ we, const float* __restrict__ wd,
                     const int* __restrict__ batch){
  __shared__ float sred[64];
  int n = blockIdx.x, c = threadIdx.x;
  const float* Fn = t ? g_F2 : g_F1;
  float se = blk64_reduce(Fn[n*NSLOT + c]*we[c], sred, c);
  if (c == 0) atomicAdd(&g_eng[batch[n]*3 + 1 + t], se);
  #pragma unroll
  for (int m = 0; m < 3; m++){
    float sd = blk64_reduce(Fn[n*NSLOT + (1+m)*64 + c]*wd[c], sred, c);
    if (c == 0) g_adip[n*3+m] += sd;
  }
}

__global__ void k_setG2(const float* __restrict__ we1){
  int i = blockIdx.x*blockDim.x + threadIdx.x;
  if (i >= NN*NSLOT) return;
  int rem = i % NSLOT; int k = rem >> 6; int c = rem & 63;
  g_G2[i] = (k == 0) ? we1[c] : 0.f;
}

__global__ void k_addwe(const float* __restrict__ we0){
  int i = blockIdx.x*blockDim.x + threadIdx.x;
  if (i >= NN*64) return;
  int n = i >> 6, c = i & 63;
  g_G1[n*NSLOT + c] += we0[c];
}

__global__ void k_polyback(int t, const float* __restrict__ wp){
  int i = blockIdx.x*blockDim.x + threadIdx.x;
  if (i >= NN*64) return;
  int n = i >> 6, c = i & 63;
  const float* M = t ? g_M1 : g_M0;
  float m[9], g[9];
  #pragma unroll
  for (int k = 0; k < 9; k++){
    m[k] = M[n*NSLOT + k*64 + c];
    g[k] = g_T1[n*NSLOT + k*64 + c];
  }
  float s0 = m[0];
  float P  = wp[c*3+0] + wp[c*3+1]*s0 + wp[c*3+2]*s0*s0;
  float dP = wp[c*3+1] + 2.f*wp[c*3+2]*s0;
  float dot = 0.f;
  #pragma unroll
  for (int k = 0; k < 9; k++) dot += g[k]*m[k];
  #pragma unroll
  for (int k = 0; k < 9; k++){
    float o = g[k]*P;
    if (k == 0) o += dot*dP;
    g_T1[n*NSLOT + k*64 + c] = o;
  }
}

// edge-parallel backward: one warp per edge, 2 channels per lane
__global__ void k_ebwd1(int t, int wte, const int* __restrict__ ei){
  int w = threadIdx.x >> 5, lane = threadIdx.x & 31;
  int e = blockIdx.x*8 + w;
  const float* F  = t ? g_F1 : g_F0;
  const float* wa = t ? g_w1 : g_w0;
  int s = ei[e], r = ei[NE+e];
  float shv[9];
  #pragma unroll
  for (int k = 0; k < 9; k++) shv[k] = g_shv[e*9+k];
  int c0 = lane, c1 = lane + 32;
  float gm0[9], gm1[9];
  #pragma unroll
  for (int k = 0; k < 9; k++){
    gm0[k] = g_A[r*NSLOT + k*64 + c0]*0.0625f;
    gm1[k] = g_A[r*NSLOT + k*64 + c1]*0.0625f;
  }
  float t10 = 0.f, t11 = 0.f;
  #pragma unroll
  for (int k = 0; k < 9; k++){ t10 += gm0[k]*shv[k]; t11 += gm1[k]*shv[k]; }
  float h0 = F[s*NSLOT + c0], h1 = F[s*NSLOT + c1];
  float w0 = wa[e*64 + c0],  w1 = wa[e*64 + c1];
  g_gw[e*64 + c0] = h0*t10;
  g_gw[e*64 + c1] = h1*t11;
  if (wte){
    g_te[e*64 + c0] = w0*t10;
    g_te[e*64 + c1] = w1*t11;
  }
  float y0 = w0*h0, y1 = w1*h1;
  float p[9];
  #pragma unroll
  for (int k = 0; k < 9; k++) p[k] = gm0[k]*y0 + gm1[k]*y1;
  #pragma unroll
  for (int off = 16; off > 0; off >>= 1)
    #pragma unroll
    for (int k = 0; k < 9; k++) p[k] += __shfl_down_sync(0xffffffffu, p[k], off);
  if (lane == 0)
    #pragma unroll
    for (int k = 0; k < 9; k++) g_gsh[e*9 + k] += p[k];
}

__global__ void k_gatherG(){
  int node = blockIdx.x*4 + (threadIdx.x >> 6);
  int c = threadIdx.x & 63;
  if (node >= NN) return;
  float acc = 0.f;
  int i1 = g_rows[node+1];
  for (int i = g_rows[node]; i < i1; i++) acc += g_te[g_eids[i]*64 + c];
  g_G1[node*NSLOT + c] += acc;
}

// MLP backward tail: gz from ga (in g_te) and recomputed z; gef += gz @ W1^T
__global__ void k_mlp2(const float* __restrict__ W1){
  __shared__ float W1s[512];
  int tid = threadIdx.x;
  for (int i = tid; i < 512; i += 256) W1s[i] = W1[i];
  __syncthreads();
  int w = tid >> 5, lane = tid & 31;
  int e = blockIdx.x*8 + w;
  float efv[8];
  #pragma unroll
  for (int b = 0; b < 8; b++) efv[b] = g_ef[e*8+b];
  int j0 = lane, j1 = lane + 32;
  float z0 = 0.f, z1 = 0.f;
  #pragma unroll
  for (int b = 0; b < 8; b++){ z0 += efv[b]*W1s[b*64+j0]; z1 += efv[b]*W1s[b*64+j1]; }
  float s0 = 1.f/(1.f + expf(-z0)), s1 = 1.f/(1.f + expf(-z1));
  float ga0 = g_te[e*64 + j0], ga1 = g_te[e*64 + j1];
  float gz0 = ga0*s0*(1.f + z0*(1.f - s0));
  float gz1 = ga1*s1*(1.f + z1*(1.f - s1));
  float p[8];
  #pragma unroll
  for (int b = 0; b < 8; b++) p[b] = gz0*W1s[b*64+j0] + gz1*W1s[b*64+j1];
  #pragma unroll
  for (int off = 16; off > 0; off >>= 1)
    #pragma unroll
    for (int b = 0; b < 8; b++) p[b] += __shfl_down_sync(0xffffffffu, p[b], off);
  if (lane == 0)
    #pragma unroll
    for (int b = 0; b < 8; b++) g_gef[e*8+b] += p[b];
}

__global__ void k_geom_bwd(const int* __restrict__ ei){
  int e = blockIdx.x*blockDim.x + threadIdx.x;
  if (e >= NE) return;
  float gl = 0.f;
  #pragma unroll
  for (int b = 0; b < 8; b++) gl += g_gef[e*8+b]*g_def[e*8+b];
  float g1 = g_gsh[e*9+1], g2 = g_gsh[e*9+2], g3 = g_gsh[e*9+3];
  float g4 = g_gsh[e*9+4], g5 = g_gsh[e*9+5], g6 = g_gsh[e*9+6];
  float g7 = g_gsh[e*9+7], g8 = g_gsh[e*9+8];
  float x = g_uhat[e*3+0], y = g_uhat[e*3+1], z = g_uhat[e*3+2];
  const float s3 = 1.7320508075688772f, s5 = 2.23606797749979f, s15 = 3.872983346207417f;
  float gux = s3*g1 + s15*(y*g4 + z*g7 + x*g8);
  float guy = s3*g2 + s15*(x*g4 + z*g5 - y*g8);
  float guz = s3*g3 + s15*(y*g5 + x*g7) + 3.f*s5*z*g6;
  float len = g_len[e];
  float gdu = gux*x + guy*y + guz*z;
  float inv = 1.f/len;
  float gvx = x*gl + (gux - x*gdu)*inv;
  float gvy = y*gl + (guy - y*gdu)*inv;
  float gvz = z*gl + (guz - z*gdu)*inv;
  int s = ei[e], r = ei[NE+e];
  atomicAdd(&g_gpos[s*3+0],  gvx);
  atomicAdd(&g_gpos[s*3+1],  gvy);
  atomicAdd(&g_gpos[s*3+2],  gvz);
  atomicAdd(&g_gpos[r*3+0], -gvx);
  atomicAdd(&g_gpos[r*3+1], -gvy);
  atomicAdd(&g_gpos[r*3+2], -gvz);
}

__global__ void k_asm_node(float* __restrict__ out, const float* __restrict__ charges,
                           const float* __restrict__ pos, const int* __restrict__ batch){
  int n = blockIdx.x*blockDim.x + threadIdx.x;
  if (n >= NN) return;
  int g = batch[n];
  float q = charges[n];
  #pragma unroll
  for (int i = 0; i < 3; i++){
    out[64 + n*3 + i] = -g_gpos[n*3+i];
    float a = g_adip[n*3+i];
    out[30112 + n*3 + i] = a;
    atomicAdd(&g_tdb[g*3+i], a + q*pos[n*3+i]);
  }
}

__global__ void k_asm_graph(float* __restrict__ out){
  int g = threadIdx.x;
  if (g >= NG) return;
  float c0 = g_eng[g*3+0], c1 = g_eng[g*3+1], c2 = g_eng[g*3+2];
  out[g] = c0 + c1 + c2;
  out[16 + g*3 + 0] = c0;
  out[16 + g*3 + 1] = c1;
  out[16 + g*3 + 2] = c2;
  #pragma unroll
  for (int i = 0; i < 3; i++) out[30064 + g*3 + i] = g_tdb[g*3+i];
}

extern "C" void kernel_launch(void* const* d_in, const int* in_sizes, int n_in,
                              void* d_out, int out_size){
  const float* pos    = (const float*)d_in[0];
  const float* attrs  = (const float*)d_in[1];
  const float* chg    = (const float*)d_in[2];
  const float* shifts = (const float*)d_in[3];
  const float* Wemb   = (const float*)d_in[4];
  const float* ae     = (const float*)d_in[5];
  const float* Wr1    = (const float*)d_in[6];
  const float* Wr2    = (const float*)d_in[7];
  const float* Wmix   = (const float*)d_in[8];
  const float* Wsc    = (const float*)d_in[9];
  const float* wpoly  = (const float*)d_in[10];
  const float* Wprod  = (const float*)d_in[11];
  const float* w_e    = (const float*)d_in[12];
  const float* w_d    = (const float*)d_in[13];
  const int*   ei     = (const int*)d_in[14];
  const int*   batch  = (const int*)d_in[15];
  float* out = (float*)d_out;

  dim3 ggN(782, 3);
  dim3 ggF(2500, 1);

  k_zero<<<(NE*9 + 255)/256, 256>>>();
  k_hist<<<NE/256, 256>>>(ei);
  k_scan<<<1, 1024>>>();
  k_fill<<<NE/256, 256>>>(ei);
  k_geom<<<NE/256, 256>>>(pos, shifts, ei);
  k_embed<<<(NN*64)/256, 256>>>(attrs, Wemb, ae, batch);

  // forward t=0
  k_mlp1<<<NE/4, 256>>>(Wr1);
  k_gemm<false,false,false,true ><<<ggF, 256>>>(9, -1, 10, -1, Wr2, 0);           // w0 = act@W2
  k_agg<<<NN/4, 256>>>(0, ei);
  k_gemm<false,false,false,false><<<ggN, 256>>>(5, -1, 3, -1, Wmix, 0);           // M0
  k_mp<<<(NN*64)/256, 256>>>(0, wpoly);
  k_gemm<false,true ,false,false><<<ggN, 256>>>(6, 0, 1, -1, Wprod, Wsc);         // F1 = T1@Wprod + F0@Wsc
  k_ed<<<NN, 64>>>(0, w_e, w_d, batch);

  // forward t=1
  k_mlp1<<<NE/4, 256>>>(Wr1 + 512);
  k_gemm<false,false,false,true ><<<ggF, 256>>>(9, -1, 11, -1, Wr2 + 4096, 0);    // w1
  k_agg<<<NN/4, 256>>>(1, ei);
  k_gemm<false,false,false,false><<<ggN, 256>>>(5, -1, 4, -1, Wmix + 12288, 0);   // M1
  k_mp<<<(NN*64)/256, 256>>>(1, wpoly + 192);
  k_gemm<false,true ,false,false><<<ggN, 256>>>(6, 1, 2, -1, Wprod + 12288, Wsc + 12288); // F2
  k_ed<<<NN, 64>>>(1, w_e + 64, w_d + 64, batch);

  // backward t=1
  k_setG2<<<(NN*NSLOT)/256, 256>>>(w_e + 64);
  k_gemm<true ,false,true ,false><<<ggN, 256>>>(7, -1, 6, 8, Wprod + 12288, Wsc + 12288); // G_T1, G_F1
  k_polyback<<<(NN*64)/256, 256>>>(1, wpoly + 192);
  k_gemm<true ,false,false,false><<<ggN, 256>>>(6, -1, 5, -1, Wmix + 12288, 0);   // G_A1
  k_ebwd1<<<NE/8, 256>>>(1, 1, ei);
  k_gatherG<<<NN/4, 256>>>();
  k_gemm<true ,false,false,true ><<<ggF, 256>>>(12, -1, 13, -1, Wr2 + 4096, 0);   // ga = gw@W2^T
  k_mlp2<<<NE/8, 256>>>(Wr1 + 512);
  k_addwe<<<(NN*64)/256, 256>>>(w_e);

  // backward t=0
  k_gemm<true ,false,false,false><<<ggN, 256>>>(8, -1, 6, -1, Wprod, 0);          // G_T1
  k_polyback<<<(NN*64)/256, 256>>>(0, wpoly);
  k_gemm<true ,false,false,false><<<ggN, 256>>>(6, -1, 5, -1, Wmix, 0);           // G_A0
  k_ebwd1<<<NE/8, 256>>>(0, 0, ei);
  k_gemm<true ,false,false,true ><<<ggF, 256>>>(12, -1, 13, -1, Wr2, 0);          // ga
  k_mlp2<<<NE/8, 256>>>(Wr1);

  k_geom_bwd<<<NE/256, 256>>>(ei);
  k_asm_node<<<(NN + 255)/256, 256>>>(out, chg, pos, batch);
  k_asm_graph<<<1, 32>>>(out);
}

// round 4
// speedup vs baseline: 1.8645x; 1.5474x over previous
#include <cuda_runtime.h>
#include <math.h>
#include <stdint.h>

#define NN 10000
#define NE 160000
#define ZZ 10
#define NG 16
#define NS4 256     // 4 slots * 64 ch
#define RMAXF 5.0f

typedef unsigned long long u64;

__device__ float g_uhat[NE*3];
__device__ float g_len [NE];
__device__ float g_ef  [NE*8];
__device__ float g_def [NE*8];
__device__ float g_act[NE*64];
__device__ float g_w0[NE*64];
__device__ float g_w1[NE*64];
__device__ float g_gw[NE*64];
__device__ float g_te[NE*64];
__device__ float g_F0[NN*NS4];
__device__ float g_F1[NN*NS4];
__device__ float g_F2[NN*NS4];
__device__ float g_M0[NN*NS4];
__device__ float g_M1[NN*NS4];
__device__ float g_A [NN*NS4];
__device__ float g_T1[NN*NS4];
__device__ float g_u [NN*64];
__device__ float g_gt[NN*64];
__device__ float g_gm[NN*64];
__device__ float g_ga[NN*64];
__device__ float g_v[128];
__device__ float g_gef[NE*8];
__device__ float g_gpos[NN*3];
__device__ float g_adip[NN*3];
__device__ float g_eng[NG*3];
__device__ float g_tdb[NG*3];
__device__ int g_degr[NN], g_degs[NN];
__device__ int g_rowr[NN+1], g_rows[NN+1];
__device__ int g_curr[NN], g_curs[NN];
__device__ int g_eidr[NE], g_eids[NE];
__device__ int g_srcr[NE];

__device__ __forceinline__ float* bufsel(int id){
  switch(id){
    case 0: return g_F0; case 1: return g_F1; case 2: return g_F2;
    case 3: return g_M0; case 4: return g_M1; case 5: return g_A;
    case 6: return g_T1; case 7: return g_act; case 8: return g_w0;
    case 9: return g_w1; case 10: return g_gw; case 11: return g_te;
    case 12: return g_u; case 13: return g_gt; case 14: return g_gm;
    default: return g_ga;
  }
}

__device__ __forceinline__ u64 dupf(unsigned x){
  u64 r; asm("mov.b64 %0,{%1,%1};" : "=l"(r) : "r"(x)); return r;
}
__device__ __forceinline__ void fma2(u64 &c, u64 a, u64 b){
  asm("fma.rn.f32x2 %0,%1,%2,%3;" : "=l"(c) : "l"(a), "l"(b), "l"(c));
}
__device__ __forceinline__ float2 asf2(u64 v){
  float2 f;
  f.x = __uint_as_float((unsigned)v);
  f.y = __uint_as_float((unsigned)(v >> 32));
  return f;
}

__global__ void k_zero(){
  int i = blockIdx.x*blockDim.x + threadIdx.x;
  if (i < NE*8) g_gef[i] = 0.f;
  if (i < NN*3) { g_gpos[i] = 0.f; g_adip[i] = 0.f; }
  if (i < NG*3) { g_eng[i] = 0.f; g_tdb[i] = 0.f; }
  if (i < NN)   { g_degr[i] = 0; g_degs[i] = 0; }
}

__global__ void k_hist(const int* __restrict__ ei){
  int e = blockIdx.x*blockDim.x + threadIdx.x;
  if (e >= NE) return;
  atomicAdd(&g_degs[ei[e]], 1);
  atomicAdd(&g_degr[ei[NE+e]], 1);
}

__global__ void k_scan(){
  __shared__ int sh[1024];
  int t = threadIdx.x;
  for (int pass = 0; pass < 2; pass++){
    int* deg = pass ? g_degs : g_degr;
    int* row = pass ? g_rows : g_rowr;
    int* cur = pass ? g_curs : g_curr;
    int base = t*10;
    int s = 0;
    for (int j = 0; j < 10; j++){ int n = base+j; if (n < NN) s += deg[n]; }
    sh[t] = s; __syncthreads();
    for (int off = 1; off < 1024; off <<= 1){
      int v = (t >= off) ? sh[t-off] : 0;
      __syncthreads();
      sh[t] += v;
      __syncthreads();
    }
    int run = sh[t] - s;
    for (int j = 0; j < 10; j++){
      int n = base+j;
      if (n < NN){ row[n] = run; cur[n] = run; run += deg[n]; }
    }
    if (t == 1023) row[NN] = sh[1023];
    __syncthreads();
  }
}

__global__ void k_fill(const int* __restrict__ ei){
  int e = blockIdx.x*blockDim.x + threadIdx.x;
  if (e >= NE) return;
  int s = ei[e], r = ei[NE+e];
  int p = atomicAdd(&g_curs[s], 1); g_eids[p] = e;
  int q = atomicAdd(&g_curr[r], 1); g_eidr[q] = e; g_srcr[q] = s;
}

__global__ void k_geom(const float* __restrict__ pos, const float* __restrict__ shifts,
                       const int* __restrict__ ei){
  int e = blockIdx.x*blockDim.x + threadIdx.x;
  if (e >= NE) return;
  int s = ei[e], r = ei[NE+e];
  float vx = pos[s*3+0] - pos[r*3+0] + shifts[e*3+0];
  float vy = pos[s*3+1] - pos[r*3+1] + shifts[e*3+1];
  float vz = pos[s*3+2] - pos[r*3+2] + shifts[e*3+2];
  float len = sqrtf(vx*vx + vy*vy + vz*vz + 1e-12f);
  float inv = 1.f/len;
  g_uhat[e*3+0] = vx*inv; g_uhat[e*3+1] = vy*inv; g_uhat[e*3+2] = vz*inv;
  g_len[e] = len;
  float u = len / RMAXF;
  float fc = 0.f, dfc = 0.f;
  if (u < 1.f){
    float u2 = u*u, u4 = u2*u2, u5 = u4*u, u6 = u5*u, u7 = u6*u;
    fc  = 1.f - 21.f*u5 + 35.f*u6 - 15.f*u7;
    dfc = (-105.f*u4 + 210.f*u5 - 105.f*u6) / RMAXF;
  }
  float ire = 1.f/(len + 1e-9f);
  float amp = 0.6324555320336759f;
  #pragma unroll
  for (int b = 0; b < 8; b++){
    float kb = (float)(b+1) * 3.14159265358979323846f / RMAXF;
    float sarg, carg;
    sincosf(kb*len, &sarg, &carg);
    float bess  = amp * sarg * ire;
    float dbess = amp * (kb*carg*ire - sarg*ire*ire);
    g_ef [e*8+b] = bess*fc;
    g_def[e*8+b] = dbess*fc + bess*dfc;
  }
}

__global__ void k_embed(const float* __restrict__ attrs, const float* __restrict__ Wemb,
                        const float* __restrict__ ae, const int* __restrict__ batch){
  int i = blockIdx.x*blockDim.x + threadIdx.x;
  if (i >= NN*64) return;
  int n = i >> 6, c = i & 63;
  float acc = 0.f;
  #pragma unroll
  for (int zq = 0; zq < ZZ; zq++) acc += attrs[n*ZZ+zq]*Wemb[zq*64+c];
  g_F0[n*NS4 + c] = acc;
  #pragma unroll
  for (int k = 1; k < 4; k++) g_F0[n*NS4 + k*64 + c] = 0.f;
  if (c == 0){
    float e0 = 0.f;
    #pragma unroll
    for (int zq = 0; zq < ZZ; zq++) e0 += attrs[n*ZZ+zq]*ae[zq];
    atomicAdd(&g_eng[batch[n]*3 + 0], e0);
  }
}

__global__ void k_mlp1(const float* __restrict__ W1){
  __shared__ float W1s[512];
  __shared__ float efs[4][8];
  int tid = threadIdx.x;
  for (int i = tid; i < 512; i += 256) W1s[i] = W1[i];
  int ebase = blockIdx.x*4;
  if (tid < 32) efs[tid>>3][tid&7] = g_ef[(ebase + (tid>>3))*8 + (tid&7)];
  __syncthreads();
  int sub = tid >> 6, j = tid & 63;
  float z = 0.f;
  #pragma unroll
  for (int b = 0; b < 8; b++) z += efs[sub][b]*W1s[b*64 + j];
  float sig = 1.f/(1.f + expf(-z));
  g_act[(ebase+sub)*64 + j] = z*sig;
}

// GEMM out = in @ Weff (Weff = W or W^T). PERL: node 4-slot layout, grid.y = l in {0,1}.
// DIN: out = in1@W1 + in2@W2. Flat mode: rows from arg, contiguous rows x 64.
template<bool TR, bool DIN, bool PERL>
__global__ void k_gemm(int in1_id, int in2_id, int out1_id,
                       const float* __restrict__ W1b, const float* __restrict__ W2b,
                       int rows_arg){
  int l  = PERL ? blockIdx.y : 0;
  int nk = PERL ? (l ? 3 : 1) : 1;
  int ks = PERL ? (l ? 1 : 0) : 0;
  int rows = PERL ? NN*nk : rows_arg;
  int rb = blockIdx.x*64;
  if (rb >= rows) return;
  const float* Wp1 = PERL ? (W1b + l*4096) : W1b;
  const float* Wp2 = DIN ? (PERL ? (W2b + l*4096) : W2b) : (const float*)0;
  __shared__ __align__(16) float As[64][66];
  __shared__ __align__(16) float Ws[64][66];
  int tid = threadIdx.x;
  int tx = tid & 15, ty = tid >> 4;
  u64 acc[2][4] = {};
  const int NP = DIN ? 2 : 1;
  #pragma unroll
  for (int p = 0; p < NP; p++){
    const float* in = bufsel((DIN && p == 1) ? in2_id : in1_id);
    const float* W  = (p == 0) ? Wp1 : Wp2;
    #pragma unroll
    for (int ii = 0; ii < 16; ii++){
      int idx = ii*256 + tid;
      int rr = idx >> 6, cc = idx & 63;
      int rg = rb + rr;
      float v = 0.f;
      if (rg < rows){
        int adr;
        if (PERL){ int n = rg/nk; int k = ks + rg%nk; adr = (n*4 + k)*64 + cc; }
        else adr = rg*64 + cc;
        v = in[adr];
      }
      As[cc][rr] = v;
      if (TR) Ws[cc][rr] = W[idx];
      else    Ws[rr][cc] = W[idx];
    }
    __syncthreads();
    #pragma unroll 4
    for (int kk = 0; kk < 64; kk++){
      const u64* ap = (const u64*)&As[kk][ty*4];
      const u64* bp = (const u64*)&Ws[kk][tx*4];
      u64 a01 = ap[0], a23 = ap[1];
      u64 b01 = bp[0], b23 = bp[1];
      u64 B0 = dupf((unsigned)b01), B1 = dupf((unsigned)(b01 >> 32));
      u64 B2 = dupf((unsigned)b23), B3 = dupf((unsigned)(b23 >> 32));
      fma2(acc[0][0], a01, B0); fma2(acc[0][1], a01, B1);
      fma2(acc[0][2], a01, B2); fma2(acc[0][3], a01, B3);
      fma2(acc[1][0], a23, B0); fma2(acc[1][1], a23, B1);
      fma2(acc[1][2], a23, B2); fma2(acc[1][3], a23, B3);
    }
    __syncthreads();
  }
  float* out = bufsel(out1_id);
  #pragma unroll
  for (int i2 = 0; i2 < 2; i2++){
    float2 c0 = asf2(acc[i2][0]), c1 = asf2(acc[i2][1]);
    float2 c2 = asf2(acc[i2][2]), c3 = asf2(acc[i2][3]);
    #pragma unroll
    for (int h = 0; h < 2; h++){
      int rg = rb + ty*4 + i2*2 + h;
      if (rg >= rows) continue;
      int adr;
      if (PERL){ int n = rg/nk; int k = ks + rg%nk; adr = (n*4 + k)*64 + tx*4; }
      else adr = rg*64 + tx*4;
      float4 v = h ? make_float4(c0.y, c1.y, c2.y, c3.y)
                   : make_float4(c0.x, c1.x, c2.x, c3.x);
      *(float4*)&out[adr] = v;
    }
  }
}

__global__ void k_agg(int t){
  int node = blockIdx.x*4 + (threadIdx.x >> 6);
  int c = threadIdx.x & 63;
  if (node >= NN) return;
  const float* Fin  = t ? g_F1 : g_F0;
  const float* warr = t ? g_w1 : g_w0;
  float a0 = 0.f, a1 = 0.f, a2 = 0.f, a3 = 0.f;
  int i1 = g_rowr[node+1];
  for (int i = g_rowr[node]; i < i1; i++){
    int e = g_eidr[i];
    int s = g_srcr[i];
    float x = Fin[s*NS4 + c] * warr[e*64 + c];
    float ux = __ldg(&g_uhat[e*3+0]);
    float uy = __ldg(&g_uhat[e*3+1]);
    float uz = __ldg(&g_uhat[e*3+2]);
    a0 += x; a1 += x*ux; a2 += x*uy; a3 += x*uz;
  }
  const float c0 = 0.0625f;
  const float c1 = 0.10825317547305482f; // sqrt(3)/16
  g_A[(node*4+0)*64 + c] = a0*c0;
  g_A[(node*4+1)*64 + c] = a1*c1;
  g_A[(node*4+2)*64 + c] = a2*c1;
  g_A[(node*4+3)*64 + c] = a3*c1;
}

__global__ void k_mp(int t, const float* __restrict__ wp){
  int i = blockIdx.x*blockDim.x + threadIdx.x;
  if (i >= NN*64) return;
  int n = i >> 6, c = i & 63;
  const float* M = t ? g_M1 : g_M0;
  float s0 = M[n*NS4 + c];
  float P = wp[c*3+0] + wp[c*3+1]*s0 + wp[c*3+2]*s0*s0;
  #pragma unroll
  for (int k = 0; k < 4; k++) g_T1[n*NS4 + k*64 + c] = M[n*NS4 + k*64 + c] * P;
}

__device__ __forceinline__ float blk64_reduce(float v, float* sred, int c){
  sred[c] = v; __syncthreads();
  if (c < 32) sred[c] += sred[c+32];
  __syncthreads();
  float r = 0.f;
  if (c < 32){
    r = sred[c];
    #pragma unroll
    for (int o = 16; o > 0; o >>= 1) r += __shfl_down_sync(0xffffffffu, r, o);
  }
  __syncthreads();
  return r;
}

__global__ void k_ed(int t, const float* __restrict__ we, const float* __restrict__ wd,
                     const int* __restrict__ batch){
  __shared__ float sred[64];
  int n = blockIdx.x, c = threadIdx.x;
  const float* Fn = t ? g_F2 : g_F1;
  float se = blk64_reduce(Fn[n*NS4 + c]*we[c], sred, c);
  if (c == 0) atomicAdd(&g_eng[batch[n]*3 + 1 + t], se);
  #pragma unroll
  for (int m = 0; m < 3; m++){
    float sd = blk64_reduce(Fn[n*NS4 + (1+m)*64 + c]*wd[c], sred, c);
    if (c == 0) g_adip[n*3+m] += sd;
  }
}

// v1 = we1 @ Wprod1[0]^T ; v2 = we1 @ Wsc1[0]^T
__global__ void k_vec(const float* __restrict__ we1, const float* __restrict__ Wp,
                      const float* __restrict__ Ws){
  int t = threadIdx.x;
  const float* W = (t < 64) ? Wp : Ws;
  int c = t & 63;
  float acc = 0.f;
  #pragma unroll
  for (int d = 0; d < 64; d++) acc += we1[d]*W[c*64+d];
  g_v[t] = acc;
}

// gM = gT * (P + s0*dP);  t selects M buf; useconst: gT = g_v[c]
__global__ void k_gm(int t, int useconst, const float* __restrict__ wp){
  int i = blockIdx.x*blockDim.x + threadIdx.x;
  if (i >= NN*64) return;
  int n = i >> 6, c = i & 63;
  const float* M = t ? g_M1 : g_M0;
  float s0 = M[n*NS4 + c];
  float P  = wp[c*3+0] + wp[c*3+1]*s0 + wp[c*3+2]*s0*s0;
  float dP = wp[c*3+1] + 2.f*wp[c*3+2]*s0;
  float gt = useconst ? g_v[c] : g_gt[i];
  g_gm[i] = gt*(P + s0*dP);
}

// per (e,c): gw = h[s]*gA[r]/16 ; optionally te = w*gA[r]/16
__global__ void k_egrad(int t, int wte, const int* __restrict__ ei){
  int i = blockIdx.x*blockDim.x + threadIdx.x;
  int e = i >> 6, c = i & 63;
  int s = ei[e], r = ei[NE+e];
  const float* F  = t ? g_F1 : g_F0;
  const float* wa = t ? g_w1 : g_w0;
  float ga = g_ga[r*64 + c]*0.0625f;
  g_gw[i] = F[s*NS4 + c]*ga;
  if (wte) g_te[i] = wa[i]*ga;
}

// u = we0 + v2 + sum over sender edges of te
__global__ void k_u0(const float* __restrict__ we0){
  int node = blockIdx.x*4 + (threadIdx.x >> 6);
  int c = threadIdx.x & 63;
  if (node >= NN) return;
  float acc = we0[c] + g_v[64+c];
  int i1 = g_rows[node+1];
  for (int i = g_rows[node]; i < i1; i++) acc += g_te[g_eids[i]*64 + c];
  g_u[node*64 + c] = acc;
}

// gz = ga*silu'(z); gef += gz @ W1^T  (ga in g_te)
__global__ void k_mlp2(const float* __restrict__ W1){
  __shared__ float W1s[512];
  int tid = threadIdx.x;
  for (int i = tid; i < 512; i += 256) W1s[i] = W1[i];
  __syncthreads();
  int w = tid >> 5, lane = tid & 31;
  int e = blockIdx.x*8 + w;
  float efv[8];
  #pragma unroll
  for (int b = 0; b < 8; b++) efv[b] = g_ef[e*8+b];
  int j0 = lane, j1 = lane + 32;
  float z0 = 0.f, z1 = 0.f;
  #pragma unroll
  for (int b = 0; b < 8; b++){ z0 += efv[b]*W1s[b*64+j0]; z1 += efv[b]*W1s[b*64+j1]; }
  float s0 = 1.f/(1.f + expf(-z0)), s1 = 1.f/(1.f + expf(-z1));
  float ga0 = g_te[e*64 + j0], ga1 = g_te[e*64 + j1];
  float gz0 = ga0*s0*(1.f + z0*(1.f - s0));
  float gz1 = ga1*s1*(1.f + z1*(1.f - s1));
  float p[8];
  #pragma unroll
  for (int b = 0; b < 8; b++) p[b] = gz0*W1s[b*64+j0] + gz1*W1s[b*64+j1];
  #pragma unroll
  for (int off = 16; off > 0; off >>= 1)
    #pragma unroll
    for (int b = 0; b < 8; b++) p[b] += __shfl_down_sync(0xffffffffu, p[b], off);
  if (lane == 0)
    #pragma unroll
    for (int b = 0; b < 8; b++) g_gef[e*8+b] += p[b];
}

__global__ void k_force(const int* __restrict__ ei){
  int e = blockIdx.x*blockDim.x + threadIdx.x;
  if (e >= NE) return;
  float gl = 0.f;
  #pragma unroll
  for (int b = 0; b < 8; b++) gl += g_gef[e*8+b]*g_def[e*8+b];
  float gvx = g_uhat[e*3+0]*gl;
  float gvy = g_uhat[e*3+1]*gl;
  float gvz = g_uhat[e*3+2]*gl;
  int s = ei[e], r = ei[NE+e];
  atomicAdd(&g_gpos[s*3+0],  gvx);
  atomicAdd(&g_gpos[s*3+1],  gvy);
  atomicAdd(&g_gpos[s*3+2],  gvz);
  atomicAdd(&g_gpos[r*3+0], -gvx);
  atomicAdd(&g_gpos[r*3+1], -gvy);
  atomicAdd(&g_gpos[r*3+2], -gvz);
}

__global__ void k_asm_node(float* __restrict__ out, const float* __restrict__ charges,
                           const float* __restrict__ pos, const int* __restrict__ batch){
  int n = blockIdx.x*blockDim.x + threadIdx.x;
  if (n >= NN) return;
  int g = batch[n];
  float q = charges[n];
  #pragma unroll
  for (int i = 0; i < 3; i++){
    out[64 + n*3 + i] = -g_gpos[n*3+i];
    float a = g_adip[n*3+i];
    out[30112 + n*3 + i] = a;
    atomicAdd(&g_tdb[g*3+i], a + q*pos[n*3+i]);
  }
}

__global__ void k_asm_graph(float* __restrict__ out){
  int g = threadIdx.x;
  if (g >= NG) return;
  float c0 = g_eng[g*3+0], c1 = g_eng[g*3+1], c2 = g_eng[g*3+2];
  out[g] = c0 + c1 + c2;
  out[16 + g*3 + 0] = c0;
  out[16 + g*3 + 1] = c1;
  out[16 + g*3 + 2] = c2;
  #pragma unroll
  for (int i = 0; i < 3; i++) out[30064 + g*3 + i] = g_tdb[g*3+i];
}

extern "C" void kernel_launch(void* const* d_in, const int* in_sizes, int n_in,
                              void* d_out, int out_size){
  const float* pos    = (const float*)d_in[0];
  const float* attrs  = (const float*)d_in[1];
  const float* chg    = (const float*)d_in[2];
  const float* shifts = (const float*)d_in[3];
  const float* Wemb   = (const float*)d_in[4];
  const float* ae     = (const float*)d_in[5];
  const float* Wr1    = (const float*)d_in[6];
  const float* Wr2    = (const float*)d_in[7];
  const float* Wmix   = (const float*)d_in[8];
  const float* Wsc    = (const float*)d_in[9];
  const float* wpoly  = (const float*)d_in[10];
  const float* Wprod  = (const float*)d_in[11];
  const float* w_e    = (const float*)d_in[12];
  const float* w_d    = (const float*)d_in[13];
  const int*   ei     = (const int*)d_in[14];
  const int*   batch  = (const int*)d_in[15];
  float* out = (float*)d_out;

  dim3 ggL(469, 2);          // per-l node GEMM (l=0: 157 active, l=1: 469)
  const int ggE = 2500;      // edge flat GEMM
  const int ggS = 157;       // NN-row flat GEMM

  k_zero<<<(NE*8 + 255)/256, 256>>>();
  k_hist<<<NE/256, 256>>>(ei);
  k_scan<<<1, 1024>>>();
  k_fill<<<NE/256, 256>>>(ei);
  k_geom<<<NE/256, 256>>>(pos, shifts, ei);
  k_embed<<<(NN*64)/256, 256>>>(attrs, Wemb, ae, batch);

  // forward t=0
  k_mlp1<<<NE/4, 256>>>(Wr1);
  k_gemm<false,false,false><<<ggE, 256>>>(7, -1, 8, Wr2, 0, NE);             // w0 = act@W2
  k_agg<<<NN/4, 256>>>(0);
  k_gemm<false,false,true ><<<ggL, 256>>>(5, -1, 3, Wmix, 0, 0);             // M0 = A@Wmix0
  k_mp<<<(NN*64)/256, 256>>>(0, wpoly);
  k_gemm<false,true ,true ><<<ggL, 256>>>(6, 0, 1, Wprod, Wsc, 0);           // F1 = T1@Wprod0 + F0@Wsc0
  k_ed<<<NN, 64>>>(0, w_e, w_d, batch);

  // forward t=1
  k_mlp1<<<NE/4, 256>>>(Wr1 + 512);
  k_gemm<false,false,false><<<ggE, 256>>>(7, -1, 9, Wr2 + 4096, 0, NE);      // w1
  k_agg<<<NN/4, 256>>>(1);
  k_gemm<false,false,true ><<<ggL, 256>>>(5, -1, 4, Wmix + 12288, 0, 0);     // M1
  k_mp<<<(NN*64)/256, 256>>>(1, wpoly + 192);
  k_gemm<false,true ,true ><<<ggL, 256>>>(6, 1, 2, Wprod + 12288, Wsc + 12288, 0); // F2
  k_ed<<<NN, 64>>>(1, w_e + 64, w_d + 64, batch);

  // backward t=1 (all slot-0; angular grads are identically zero)
  k_vec<<<1, 128>>>(w_e + 64, Wprod + 12288, Wsc + 12288);
  k_gm<<<(NN*64)/256, 256>>>(1, 1, wpoly + 192);                             // gM1
  k_gemm<true ,false,false><<<ggS, 256>>>(14, -1, 15, Wmix + 12288, 0, NN);  // gA1 = gM1@Wmix1[0]^T
  k_egrad<<<NE*64/256, 256>>>(1, 1, ei);                                     // gw1, te
  k_u0<<<NN/4, 256>>>(w_e);                                                  // u = we0+v2+gather(te)
  k_gemm<true ,false,false><<<ggE, 256>>>(10, -1, 11, Wr2 + 4096, 0, NE);    // ga = gw@W2^T
  k_mlp2<<<NE/8, 256>>>(Wr1 + 512);

  // backward t=0
  k_gemm<true ,false,false><<<ggS, 256>>>(12, -1, 13, Wprod, 0, NN);         // gT0 = u@Wprod0[0]^T
  k_gm<<<(NN*64)/256, 256>>>(0, 0, wpoly);                                   // gM0
  k_gemm<true ,false,false><<<ggS, 256>>>(14, -1, 15, Wmix, 0, NN);          // gA0
  k_egrad<<<NE*64/256, 256>>>(0, 1, ei);                                     // gw0 (te unused later but harmless)
  k_gemm<true ,false,false><<<ggE, 256>>>(10, -1, 11, Wr2, 0, NE);           // ga
  k_mlp2<<<NE/8, 256>>>(Wr1);

  k_force<<<NE/256, 256>>>(ei);
  k_asm_node<<<(NN + 255)/256, 256>>>(out, chg, pos, batch);
  k_asm_graph<<<1, 32>>>(out);
}

// round 5
// speedup vs baseline: 2.1001x; 1.1263x over previous
#include <cuda_runtime.h>
#include <math.h>
#include <stdint.h>

#define NN 10000
#define NE 160000
#define ZZ 10
#define NG 16
#define NS4 256
#define RMAXF 5.0f

typedef unsigned long long u64;

__device__ float g_uhat[NE*3];
__device__ float g_len [NE];
__device__ float g_ef  [NE*8];
__device__ float g_def [NE*8];
__device__ float g_act[NE*64];
__device__ float g_w0[NE*64];
__device__ float g_w1[NE*64];
__device__ float g_te[NE*64];
__device__ float g_F0[NN*NS4];
__device__ float g_F1[NN*NS4];
__device__ float g_F2[NN*NS4];
__device__ float g_M0[NN*NS4];
__device__ float g_M1[NN*NS4];
__device__ float g_A [NN*NS4];
__device__ float g_u [NN*64];
__device__ float g_gt[NN*64];
__device__ float g_ga[NN*64];
__device__ float g_v[128];
__device__ float g_gef[NE*8];
__device__ float g_en[3*NN];
__device__ float g_gpos[NN*3];
__device__ float g_adip[NN*3];
__device__ float g_eng[NG*3];
__device__ float g_tdb[NG*3];
__device__ int g_degr[NN], g_degs[NN];
__device__ int g_rowr[NN+1], g_rows[NN+1];
__device__ int g_curr[NN], g_curs[NN];
__device__ int g_eidr[NE], g_eids[NE];
__device__ int g_srcr[NE];

__device__ __forceinline__ float* bufsel(int id){
  switch(id){
    case 0: return g_F0; case 1: return g_F1; case 2: return g_F2;
    case 3: return g_M0; case 4: return g_M1; case 5: return g_A;
    case 6: return g_act; case 7: return g_w0; case 8: return g_w1;
    case 9: return g_te; case 10: return g_u; case 11: return g_gt;
    default: return g_ga;
  }
}

__device__ __forceinline__ u64 dupf(unsigned x){
  u64 r; asm("mov.b64 %0,{%1,%1};" : "=l"(r) : "r"(x)); return r;
}
__device__ __forceinline__ void fma2(u64 &c, u64 a, u64 b){
  asm("fma.rn.f32x2 %0,%1,%2,%3;" : "=l"(c) : "l"(a), "l"(b), "l"(c));
}
__device__ __forceinline__ float2 asf2(u64 v){
  float2 f;
  f.x = __uint_as_float((unsigned)v);
  f.y = __uint_as_float((unsigned)(v >> 32));
  return f;
}

__global__ void k_zero(){
  int i = blockIdx.x*blockDim.x + threadIdx.x;
  if (i < NN*3) g_gpos[i] = 0.f;
  if (i < NG*3) { g_eng[i] = 0.f; g_tdb[i] = 0.f; }
  if (i < NN)   { g_degr[i] = 0; g_degs[i] = 0; }
}

__global__ void k_geom(const float* __restrict__ pos, const float* __restrict__ shifts,
                       const int* __restrict__ ei){
  int e = blockIdx.x*blockDim.x + threadIdx.x;
  if (e >= NE) return;
  int s = ei[e], r = ei[NE+e];
  atomicAdd(&g_degs[s], 1);
  atomicAdd(&g_degr[r], 1);
  float vx = pos[s*3+0] - pos[r*3+0] + shifts[e*3+0];
  float vy = pos[s*3+1] - pos[r*3+1] + shifts[e*3+1];
  float vz = pos[s*3+2] - pos[r*3+2] + shifts[e*3+2];
  float len = sqrtf(vx*vx + vy*vy + vz*vz + 1e-12f);
  float inv = 1.f/len;
  g_uhat[e*3+0] = vx*inv; g_uhat[e*3+1] = vy*inv; g_uhat[e*3+2] = vz*inv;
  g_len[e] = len;
  float u = len / RMAXF;
  float fc = 0.f, dfc = 0.f;
  if (u < 1.f){
    float u2 = u*u, u4 = u2*u2, u5 = u4*u, u6 = u5*u, u7 = u6*u;
    fc  = 1.f - 21.f*u5 + 35.f*u6 - 15.f*u7;
    dfc = (-105.f*u4 + 210.f*u5 - 105.f*u6) / RMAXF;
  }
  float ire = 1.f/(len + 1e-9f);
  const float amp = 0.6324555320336759f;
  const float PIC = 3.14159265358979323846f;
  float th = PIC*len/RMAXF;
  float s1, c1;
  sincosf(th, &s1, &c1);
  float twoc = 2.f*c1;
  float sp = 0.f, cp = 1.f, sc = s1, cc = c1;
  #pragma unroll
  for (int b = 0; b < 8; b++){
    float kb = (float)(b+1)*PIC/RMAXF;
    float bess  = amp*sc*ire;
    float dbess = amp*(kb*cc*ire - sc*ire*ire);
    g_ef [e*8+b] = bess*fc;
    g_def[e*8+b] = dbess*fc + bess*dfc;
    float sn = twoc*sc - sp, cn = twoc*cc - cp;
    sp = sc; cp = cc; sc = sn; cc = cn;
  }
}

__global__ void k_scan(){
  __shared__ int sh[1024];
  int t = threadIdx.x;
  for (int pass = 0; pass < 2; pass++){
    int* deg = pass ? g_degs : g_degr;
    int* row = pass ? g_rows : g_rowr;
    int* cur = pass ? g_curs : g_curr;
    int base = t*10;
    int s = 0;
    for (int j = 0; j < 10; j++){ int n = base+j; if (n < NN) s += deg[n]; }
    sh[t] = s; __syncthreads();
    for (int off = 1; off < 1024; off <<= 1){
      int v = (t >= off) ? sh[t-off] : 0;
      __syncthreads();
      sh[t] += v;
      __syncthreads();
    }
    int run = sh[t] - s;
    for (int j = 0; j < 10; j++){
      int n = base+j;
      if (n < NN){ row[n] = run; cur[n] = run; run += deg[n]; }
    }
    if (t == 1023) row[NN] = sh[1023];
    __syncthreads();
  }
}

__global__ void k_fill(const int* __restrict__ ei){
  int e = blockIdx.x*blockDim.x + threadIdx.x;
  if (e >= NE) return;
  int s = ei[e], r = ei[NE+e];
  int p = atomicAdd(&g_curs[s], 1); g_eids[p] = e;
  int q = atomicAdd(&g_curr[r], 1); g_eidr[q] = e; g_srcr[q] = s;
}

__global__ void k_embed(const float* __restrict__ attrs, const float* __restrict__ Wemb,
                        const float* __restrict__ ae){
  int i = blockIdx.x*blockDim.x + threadIdx.x;
  if (i >= NN*64) return;
  int n = i >> 6, c = i & 63;
  float acc = 0.f;
  #pragma unroll
  for (int zq = 0; zq < ZZ; zq++) acc += attrs[n*ZZ+zq]*Wemb[zq*64+c];
  g_F0[n*NS4 + c] = acc;
  #pragma unroll
  for (int k = 1; k < 4; k++) g_F0[n*NS4 + k*64 + c] = 0.f;
  if (c == 0){
    float e0 = 0.f;
    #pragma unroll
    for (int zq = 0; zq < ZZ; zq++) e0 += attrs[n*ZZ+zq]*ae[zq];
    g_en[n] = e0;
  }
}

__global__ void k_mlp1(const float* __restrict__ W1){
  __shared__ float W1s[512];
  __shared__ float efs[4][8];
  int tid = threadIdx.x;
  for (int i = tid; i < 512; i += 256) W1s[i] = W1[i];
  int ebase = blockIdx.x*4;
  if (tid < 32) efs[tid>>3][tid&7] = g_ef[(ebase + (tid>>3))*8 + (tid&7)];
  __syncthreads();
  int sub = tid >> 6, j = tid & 63;
  float z = 0.f;
  #pragma unroll
  for (int b = 0; b < 8; b++) z += efs[sub][b]*W1s[b*64 + j];
  float sig = 1.f/(1.f + expf(-z));
  g_act[(ebase+sub)*64 + j] = z*sig;
}

// AM: 0 plain, 1 poly-fwd (PERL DIN p0), 2 gw-inline (edges), 3 gM1 from const v, 4 gM0 from gt
template<int AM, bool TR, bool DIN, bool PERL, int TM>
__global__ void k_gemm(int in1, int in2, int out_id,
                       const float* __restrict__ W1b, const float* __restrict__ W2b,
                       const float* __restrict__ wp, const int* __restrict__ ei,
                       int t, int rows_arg){
  int l  = PERL ? blockIdx.y : 0;
  int nk = PERL ? (l ? 3 : 1) : 1;
  int ks = PERL ? (l ? 1 : 0) : 0;
  int rows = PERL ? NN*nk : rows_arg;
  int rb = blockIdx.x*TM;
  if (rb >= rows) return;
  const float* Wp1 = PERL ? (W1b + l*4096) : W1b;
  const float* Wp2 = DIN ? (PERL ? (W2b + l*4096) : W2b) : (const float*)0;
  __shared__ __align__(16) float As[64][TM+2];
  __shared__ __align__(16) float Ws[64][66];
  int tid = threadIdx.x;
  int tx = tid & 15, ty = tid >> 4;
  const int RT = TM/16;
  u64 acc[RT/2][4];
  #pragma unroll
  for (int i = 0; i < RT/2; i++)
    #pragma unroll
    for (int j = 0; j < 4; j++) acc[i][j] = 0ull;
  const int NP = DIN ? 2 : 1;
  #pragma unroll
  for (int p = 0; p < NP; p++){
    const float* W = (p == 0) ? Wp1 : Wp2;
    #pragma unroll
    for (int ii = 0; ii < TM/4; ii++){
      int idx = ii*256 + tid;
      int rr = idx >> 6, cc = idx & 63;
      int rg = rb + rr;
      float v = 0.f;
      if (rg < rows){
        if (AM == 1 && p == 0){
          const float* M = t ? g_M1 : g_M0;
          int n = rg/nk, k = ks + rg%nk;
          float s0 = M[n*NS4 + cc];
          float P = wp[cc*3+0] + wp[cc*3+1]*s0 + wp[cc*3+2]*s0*s0;
          v = M[(n*4+k)*64 + cc]*P;
        } else if (AM == 2 && p == 0){
          int s = ei[rg], r = ei[NE+rg];
          const float* F = t ? g_F1 : g_F0;
          v = F[s*NS4 + cc]*g_ga[r*64 + cc]*0.0625f;
        } else if (AM == 3 && p == 0){
          float s0 = g_M1[rg*NS4 + cc];
          v = g_v[cc]*(wp[cc*3+0] + 2.f*wp[cc*3+1]*s0 + 3.f*wp[cc*3+2]*s0*s0);
        } else if (AM == 4 && p == 0){
          float s0 = g_M0[rg*NS4 + cc];
          v = g_gt[rg*64 + cc]*(wp[cc*3+0] + 2.f*wp[cc*3+1]*s0 + 3.f*wp[cc*3+2]*s0*s0);
        } else {
          const float* in = bufsel((DIN && p == 1) ? in2 : in1);
          int adr;
          if (PERL){ int n = rg/nk, k = ks + rg%nk; adr = (n*4+k)*64 + cc; }
          else adr = rg*64 + cc;
          v = in[adr];
        }
      }
      As[cc][rr] = v;
    }
    #pragma unroll
    for (int ii = 0; ii < 16; ii++){
      int idx = ii*256 + tid;
      int rr = idx >> 6, cc = idx & 63;
      if (TR) Ws[cc][rr] = W[idx];
      else    Ws[rr][cc] = W[idx];
    }
    __syncthreads();
    #pragma unroll 4
    for (int kk = 0; kk < 64; kk++){
      const u64* ap = (const u64*)&As[kk][ty*RT];
      const u64* bp = (const u64*)&Ws[kk][tx*4];
      u64 b01 = bp[0], b23 = bp[1];
      u64 B0 = dupf((unsigned)b01), B1 = dupf((unsigned)(b01 >> 32));
      u64 B2 = dupf((unsigned)b23), B3 = dupf((unsigned)(b23 >> 32));
      #pragma unroll
      for (int i = 0; i < RT/2; i++){
        u64 a = ap[i];
        fma2(acc[i][0], a, B0); fma2(acc[i][1], a, B1);
        fma2(acc[i][2], a, B2); fma2(acc[i][3], a, B3);
      }
    }
    __syncthreads();
  }
  float* out = bufsel(out_id);
  #pragma unroll
  for (int i = 0; i < RT/2; i++){
    float2 c0 = asf2(acc[i][0]), c1 = asf2(acc[i][1]);
    float2 c2 = asf2(acc[i][2]), c3 = asf2(acc[i][3]);
    #pragma unroll
    for (int h = 0; h < 2; h++){
      int rg = rb + ty*RT + i*2 + h;
      if (rg >= rows) continue;
      int adr;
      if (PERL){ int n = rg/nk, k = ks + rg%nk; adr = (n*4+k)*64 + tx*4; }
      else adr = rg*64 + tx*4;
      float4 v = h ? make_float4(c0.y, c1.y, c2.y, c3.y)
                   : make_float4(c0.x, c1.x, c2.x, c3.x);
      *(float4*)&out[adr] = v;
    }
  }
}

__global__ void k_agg(int t){
  int node = blockIdx.x*4 + (threadIdx.x >> 6);
  int c = threadIdx.x & 63;
  if (node >= NN) return;
  const float* Fin  = t ? g_F1 : g_F0;
  const float* warr = t ? g_w1 : g_w0;
  float a0 = 0.f, a1 = 0.f, a2 = 0.f, a3 = 0.f;
  int i1 = g_rowr[node+1];
  for (int i = g_rowr[node]; i < i1; i++){
    int e = g_eidr[i];
    int s = g_srcr[i];
    float x = Fin[s*NS4 + c] * warr[e*64 + c];
    float ux = __ldg(&g_uhat[e*3+0]);
    float uy = __ldg(&g_uhat[e*3+1]);
    float uz = __ldg(&g_uhat[e*3+2]);
    a0 += x; a1 += x*ux; a2 += x*uy; a3 += x*uz;
  }
  const float c0 = 0.0625f;
  const float c1 = 0.10825317547305482f;
  g_A[(node*4+0)*64 + c] = a0*c0;
  g_A[(node*4+1)*64 + c] = a1*c1;
  g_A[(node*4+2)*64 + c] = a2*c1;
  g_A[(node*4+3)*64 + c] = a3*c1;
}

__device__ __forceinline__ float blk64_reduce(float v, float* sred, int c){
  sred[c] = v; __syncthreads();
  if (c < 32) sred[c] += sred[c+32];
  __syncthreads();
  float r = 0.f;
  if (c < 32){
    r = sred[c];
    #pragma unroll
    for (int o = 16; o > 0; o >>= 1) r += __shfl_down_sync(0xffffffffu, r, o);
  }
  __syncthreads();
  return r;
}

__global__ void k_ed(int t, const float* __restrict__ we, const float* __restrict__ wd){
  __shared__ float sred[64];
  int n = blockIdx.x, c = threadIdx.x;
  const float* Fn = t ? g_F2 : g_F1;
  float se = blk64_reduce(Fn[n*NS4 + c]*we[c], sred, c);
  if (c == 0) g_en[(1+t)*NN + n] = se;
  #pragma unroll
  for (int m = 0; m < 3; m++){
    float sd = blk64_reduce(Fn[n*NS4 + (1+m)*64 + c]*wd[c], sred, c);
    if (c == 0){
      if (t) g_adip[n*3+m] += sd;
      else   g_adip[n*3+m]  = sd;
    }
  }
}

__global__ void k_gsum(const float* __restrict__ chg, const float* __restrict__ pos,
                       const int* __restrict__ batch){
  __shared__ float bins[96];
  int tid = threadIdx.x;
  if (tid < 96) bins[tid] = 0.f;
  __syncthreads();
  int n = blockIdx.x*256 + tid;
  if (n < NN){
    int g = batch[n];
    atomicAdd(&bins[g*6+0], g_en[n]);
    atomicAdd(&bins[g*6+1], g_en[NN+n]);
    atomicAdd(&bins[g*6+2], g_en[2*NN+n]);
    float q = chg[n];
    #pragma unroll
    for (int j = 0; j < 3; j++)
      atomicAdd(&bins[g*6+3+j], g_adip[n*3+j] + q*pos[n*3+j]);
  }
  __syncthreads();
  if (tid < 96){
    int g = tid/6, j = tid%6;
    float v = bins[tid];
    if (j < 3) atomicAdd(&g_eng[g*3+j], v);
    else       atomicAdd(&g_tdb[g*3+j-3], v);
  }
}

__global__ void k_vec(const float* __restrict__ we1, const float* __restrict__ Wp,
                      const float* __restrict__ Ws){
  int t = threadIdx.x;
  const float* W = (t < 64) ? Wp : Ws;
  int c = t & 63;
  float acc = 0.f;
  #pragma unroll
  for (int d = 0; d < 64; d++) acc += we1[d]*W[c*64+d];
  g_v[t] = acc;
}

__global__ void k_u0(const float* __restrict__ we0, const int* __restrict__ ei){
  int node = blockIdx.x*4 + (threadIdx.x >> 6);
  int c = threadIdx.x & 63;
  if (node >= NN) return;
  float acc = we0[c] + g_v[64+c];
  int i1 = g_rows[node+1];
  for (int i = g_rows[node]; i < i1; i++){
    int e = g_eids[i];
    int r = ei[NE+e];
    acc += g_w1[e*64+c]*g_ga[r*64+c]*0.0625f;
  }
  g_u[node*64 + c] = acc;
}

template<bool FINAL>
__global__ void k_mlp2(const float* __restrict__ W1, const int* __restrict__ ei){
  __shared__ float W1s[512];
  int tid = threadIdx.x;
  for (int i = tid; i < 512; i += 256) W1s[i] = W1[i];
  __syncthreads();
  int w = tid >> 5, lane = tid & 31;
  int e = blockIdx.x*8 + w;
  float efv[8];
  #pragma unroll
  for (int b = 0; b < 8; b++) efv[b] = g_ef[e*8+b];
  int j0 = lane, j1 = lane + 32;
  float z0 = 0.f, z1 = 0.f;
  #pragma unroll
  for (int b = 0; b < 8; b++){ z0 += efv[b]*W1s[b*64+j0]; z1 += efv[b]*W1s[b*64+j1]; }
  float s0 = 1.f/(1.f + expf(-z0)), s1 = 1.f/(1.f + expf(-z1));
  float ga0 = g_te[e*64 + j0], ga1 = g_te[e*64 + j1];
  float gz0 = ga0*s0*(1.f + z0*(1.f - s0));
  float gz1 = ga1*s1*(1.f + z1*(1.f - s1));
  float p[8];
  #pragma unroll
  for (int b = 0; b < 8; b++) p[b] = gz0*W1s[b*64+j0] + gz1*W1s[b*64+j1];
  #pragma unroll
  for (int off = 16; off > 0; off >>= 1)
    #pragma unroll
    for (int b = 0; b < 8; b++) p[b] += __shfl_down_sync(0xffffffffu, p[b], off);
  if (lane == 0){
    if (!FINAL){
      #pragma unroll
      for (int b = 0; b < 8; b++) g_gef[e*8+b] = p[b];
    } else {
      float gl = 0.f;
      #pragma unroll
      for (int b = 0; b < 8; b++) gl += (g_gef[e*8+b] + p[b])*g_def[e*8+b];
      float gvx = g_uhat[e*3+0]*gl;
      float gvy = g_uhat[e*3+1]*gl;
      float gvz = g_uhat[e*3+2]*gl;
      int s = ei[e], r = ei[NE+e];
      atomicAdd(&g_gpos[s*3+0],  gvx);
      atomicAdd(&g_gpos[s*3+1],  gvy);
      atomicAdd(&g_gpos[s*3+2],  gvz);
      atomicAdd(&g_gpos[r*3+0], -gvx);
      atomicAdd(&g_gpos[r*3+1], -gvy);
      atomicAdd(&g_gpos[r*3+2], -gvz);
    }
  }
}

__global__ void k_asm_node(float* __restrict__ out){
  int n = blockIdx.x*blockDim.x + threadIdx.x;
  if (n >= NN) return;
  #pragma unroll
  for (int i = 0; i < 3; i++){
    out[64 + n*3 + i] = -g_gpos[n*3+i];
    out[30112 + n*3 + i] = g_adip[n*3+i];
  }
}

__global__ void k_asm_graph(float* __restrict__ out){
  int g = threadIdx.x;
  if (g >= NG) return;
  float c0 = g_eng[g*3+0], c1 = g_eng[g*3+1], c2 = g_eng[g*3+2];
  out[g] = c0 + c1 + c2;
  out[16 + g*3 + 0] = c0;
  out[16 + g*3 + 1] = c1;
  out[16 + g*3 + 2] = c2;
  #pragma unroll
  for (int i = 0; i < 3; i++) out[30064 + g*3 + i] = g_tdb[g*3+i];
}

extern "C" void kernel_launch(void* const* d_in, const int* in_sizes, int n_in,
                              void* d_out, int out_size){
  const float* pos    = (const float*)d_in[0];
  const float* attrs  = (const float*)d_in[1];
  const float* chg    = (const float*)d_in[2];
  const float* shifts = (const float*)d_in[3];
  const float* Wemb   = (const float*)d_in[4];
  const float* ae     = (const float*)d_in[5];
  const float* Wr1    = (const float*)d_in[6];
  const float* Wr2    = (const float*)d_in[7];
  const float* Wmix   = (const float*)d_in[8];
  const float* Wsc    = (const float*)d_in[9];
  const float* wpoly  = (const float*)d_in[10];
  const float* Wprod  = (const float*)d_in[11];
  const float* w_e    = (const float*)d_in[12];
  const float* w_d    = (const float*)d_in[13];
  const int*   ei     = (const int*)d_in[14];
  const int*   batch  = (const int*)d_in[15];
  float* out = (float*)d_out;

  dim3 ggL(469, 2);
  const int ggE = (NE + 95)/96;   // 1667
  const int ggS = (NN + 95)/96;   // 105

  k_zero<<<(NN*3 + 255)/256, 256>>>();
  k_geom<<<NE/256, 256>>>(pos, shifts, ei);
  k_scan<<<1, 1024>>>();
  k_fill<<<NE/256, 256>>>(ei);
  k_embed<<<(NN*64)/256, 256>>>(attrs, Wemb, ae);

  // forward t=0
  k_mlp1<<<NE/4, 256>>>(Wr1);
  k_gemm<0,false,false,false,96><<<ggE, 256>>>(6, -1, 7, Wr2, 0, 0, 0, 0, NE);
  k_agg<<<NN/4, 256>>>(0);
  k_gemm<0,false,false,true ,64><<<ggL, 256>>>(5, -1, 3, Wmix, 0, 0, 0, 0, 0);
  k_gemm<1,false,true ,true ,64><<<ggL, 256>>>(-1, 0, 1, Wprod, Wsc, wpoly, 0, 0, 0);
  k_ed<<<NN, 64>>>(0, w_e, w_d);

  // forward t=1
  k_mlp1<<<NE/4, 256>>>(Wr1 + 512);
  k_gemm<0,false,false,false,96><<<ggE, 256>>>(6, -1, 8, Wr2 + 4096, 0, 0, 0, 0, NE);
  k_agg<<<NN/4, 256>>>(1);
  k_gemm<0,false,false,true ,64><<<ggL, 256>>>(5, -1, 4, Wmix + 12288, 0, 0, 0, 0, 0);
  k_gemm<1,false,true ,true ,64><<<ggL, 256>>>(-1, 1, 2, Wprod + 12288, Wsc + 12288, wpoly + 192, 0, 1, 0);
  k_ed<<<NN, 64>>>(1, w_e + 64, w_d + 64);
  k_gsum<<<(NN + 255)/256, 256>>>(chg, pos, batch);

  // backward t=1
  k_vec<<<1, 128>>>(w_e + 64, Wprod + 12288, Wsc + 12288);
  k_gemm<3,true ,false,false,96><<<ggS, 256>>>(-1, -1, 12, Wmix + 12288, 0, wpoly + 192, 0, 1, NN);
  k_u0<<<NN/4, 256>>>(w_e, ei);
  k_gemm<2,true ,false,false,96><<<ggE, 256>>>(-1, -1, 9, Wr2 + 4096, 0, 0, ei, 1, NE);
  k_mlp2<false><<<NE/8, 256>>>(Wr1 + 512, ei);

  // backward t=0
  k_gemm<0,true ,false,false,96><<<ggS, 256>>>(10, -1, 11, Wprod, 0, 0, 0, 0, NN);
  k_gemm<4,true ,false,false,96><<<ggS, 256>>>(-1, -1, 12, Wmix, 0, wpoly, 0, 0, NN);
  k_gemm<2,true ,false,false,96><<<ggE, 256>>>(-1, -1, 9, Wr2, 0, 0, ei, 0, NE);
  k_mlp2<true ><<<NE/8, 256>>>(Wr1, ei);

  k_asm_node<<<(NN + 255)/256, 256>>>(out);
  k_asm_graph<<<1, 32>>>(out);
}

// round 7
// speedup vs baseline: 2.1483x; 1.0230x over previous
#include <cuda_runtime.h>
#include <math.h>
#include <stdint.h>

#define NN 10000
#define NE 160000
#define ZZ 10
#define NG 16
#define NS4 256
#define RMAXF 5.0f

typedef unsigned long long u64;

__device__ float g_uhat[NE*3];
__device__ float g_len [NE];
__device__ float g_ef  [NE*8];
__device__ float g_def [NE*8];
__device__ float g_act[NE*64];
__device__ float g_w0[NE*64];
__device__ float g_w1[NE*64];
__device__ float g_F0[NN*NS4];
__device__ float g_F1[NN*NS4];
__device__ float g_F2[NN*NS4];
__device__ float g_M0[NN*NS4];
__device__ float g_M1[NN*NS4];
__device__ float g_A [NN*NS4];
__device__ float g_u [NN*64];
__device__ float g_gt[NN*64];
__device__ float g_ga[NN*64];
__device__ float g_v[128];
__device__ float g_gef[NE*8];
__device__ float g_en[3*NN];
__device__ float g_gpos[NN*3];
__device__ float g_adip[NN*3];
__device__ float g_eng[NG*3];
__device__ float g_tdb[NG*3];
__device__ int g_degr[NN], g_degs[NN];
__device__ int g_rowr[NN+1], g_rows[NN+1];
__device__ int g_curr[NN], g_curs[NN];
__device__ int g_eidr[NE], g_eids[NE];
__device__ int g_srcr[NE];

__device__ __forceinline__ float* bufsel(int id){
  switch(id){
    case 0: return g_F0; case 1: return g_F1; case 2: return g_F2;
    case 3: return g_M0; case 4: return g_M1; case 5: return g_A;
    case 6: return g_act; case 7: return g_w0; case 8: return g_w1;
    case 9: return g_u; case 10: return g_gt; default: return g_ga;
  }
}

__device__ __forceinline__ u64 dupf(unsigned x){
  u64 r; asm("mov.b64 %0,{%1,%1};" : "=l"(r) : "r"(x)); return r;
}
__device__ __forceinline__ void fma2(u64 &c, u64 a, u64 b){
  asm("fma.rn.f32x2 %0,%1,%2,%3;" : "=l"(c) : "l"(a), "l"(b), "l"(c));
}
__device__ __forceinline__ float2 asf2(u64 v){
  float2 f;
  f.x = __uint_as_float((unsigned)v);
  f.y = __uint_as_float((unsigned)(v >> 32));
  return f;
}

__global__ void k_zero(){
  int i = blockIdx.x*blockDim.x + threadIdx.x;
  if (i < NN*3) g_gpos[i] = 0.f;
  if (i < NG*3) { g_eng[i] = 0.f; g_tdb[i] = 0.f; }
  if (i < NN)   { g_degr[i] = 0; g_degs[i] = 0; }
}

__global__ void k_geom(const float* __restrict__ pos, const float* __restrict__ shifts,
                       const int* __restrict__ ei){
  int e = blockIdx.x*blockDim.x + threadIdx.x;
  if (e >= NE) return;
  int s = ei[e], r = ei[NE+e];
  atomicAdd(&g_degs[s], 1);
  atomicAdd(&g_degr[r], 1);
  float vx = pos[s*3+0] - pos[r*3+0] + shifts[e*3+0];
  float vy = pos[s*3+1] - pos[r*3+1] + shifts[e*3+1];
  float vz = pos[s*3+2] - pos[r*3+2] + shifts[e*3+2];
  float len = sqrtf(vx*vx + vy*vy + vz*vz + 1e-12f);
  float inv = 1.f/len;
  g_uhat[e*3+0] = vx*inv; g_uhat[e*3+1] = vy*inv; g_uhat[e*3+2] = vz*inv;
  g_len[e] = len;
  float u = len / RMAXF;
  float fc = 0.f, dfc = 0.f;
  if (u < 1.f){
    float u2 = u*u, u4 = u2*u2, u5 = u4*u, u6 = u5*u, u7 = u6*u;
    fc  = 1.f - 21.f*u5 + 35.f*u6 - 15.f*u7;
    dfc = (-105.f*u4 + 210.f*u5 - 105.f*u6) / RMAXF;
  }
  float ire = 1.f/(len + 1e-9f);
  const float amp = 0.6324555320336759f;
  const float PIC = 3.14159265358979323846f;
  float th = PIC*len/RMAXF;
  float s1, c1;
  sincosf(th, &s1, &c1);
  float twoc = 2.f*c1;
  float sp = 0.f, cp = 1.f, sc = s1, cc = c1;
  #pragma unroll
  for (int b = 0; b < 8; b++){
    float kb = (float)(b+1)*PIC/RMAXF;
    float bess  = amp*sc*ire;
    float dbess = amp*(kb*cc*ire - sc*ire*ire);
    g_ef [e*8+b] = bess*fc;
    g_def[e*8+b] = dbess*fc + bess*dfc;
    float sn = twoc*sc - sp, cn = twoc*cc - cp;
    sp = sc; cp = cc; sc = sn; cc = cn;
  }
}

__global__ void k_scan(){
  __shared__ int sh[1024];
  int t = threadIdx.x;
  for (int pass = 0; pass < 2; pass++){
    int* deg = pass ? g_degs : g_degr;
    int* row = pass ? g_rows : g_rowr;
    int* cur = pass ? g_curs : g_curr;
    int base = t*10;
    int s = 0;
    for (int j = 0; j < 10; j++){ int n = base+j; if (n < NN) s += deg[n]; }
    sh[t] = s; __syncthreads();
    for (int off = 1; off < 1024; off <<= 1){
      int v = (t >= off) ? sh[t-off] : 0;
      __syncthreads();
      sh[t] += v;
      __syncthreads();
    }
    int run = sh[t] - s;
    for (int j = 0; j < 10; j++){
      int n = base+j;
      if (n < NN){ row[n] = run; cur[n] = run; run += deg[n]; }
    }
    if (t == 1023) row[NN] = sh[1023];
    __syncthreads();
  }
}

__global__ void k_fill(const int* __restrict__ ei){
  int e = blockIdx.x*blockDim.x + threadIdx.x;
  if (e >= NE) return;
  int s = ei[e], r = ei[NE+e];
  int p = atomicAdd(&g_curs[s], 1); g_eids[p] = e;
  int q = atomicAdd(&g_curr[r], 1); g_eidr[q] = e; g_srcr[q] = s;
}

__global__ void k_embed(const float* __restrict__ attrs, const float* __restrict__ Wemb,
                        const float* __restrict__ ae){
  int i = blockIdx.x*blockDim.x + threadIdx.x;
  if (i >= NN*64) return;
  int n = i >> 6, c = i & 63;
  float acc = 0.f;
  #pragma unroll
  for (int zq = 0; zq < ZZ; zq++) acc += attrs[n*ZZ+zq]*Wemb[zq*64+c];
  g_F0[n*NS4 + c] = acc;
  #pragma unroll
  for (int k = 1; k < 4; k++) g_F0[n*NS4 + k*64 + c] = 0.f;
  if (c == 0){
    float e0 = 0.f;
    #pragma unroll
    for (int zq = 0; zq < ZZ; zq++) e0 += attrs[n*ZZ+zq]*ae[zq];
    g_en[n] = e0;
  }
}

__global__ void k_mlp1(const float* __restrict__ W1){
  __shared__ float W1s[512];
  __shared__ float efs[4][8];
  int tid = threadIdx.x;
  for (int i = tid; i < 512; i += 256) W1s[i] = W1[i];
  int ebase = blockIdx.x*4;
  if (tid < 32) efs[tid>>3][tid&7] = g_ef[(ebase + (tid>>3))*8 + (tid&7)];
  __syncthreads();
  int sub = tid >> 6, j = tid & 63;
  float z = 0.f;
  #pragma unroll
  for (int b = 0; b < 8; b++) z += efs[sub][b]*W1s[b*64 + j];
  float sig = 1.f/(1.f + expf(-z));
  g_act[(ebase+sub)*64 + j] = z*sig;
}

// AM: 0 plain, 1 poly-fwd (DIN p0 from M), 3 gM1-from-g_v, 4 gM0-from-gt
template<int AM, bool TR, bool DIN, bool PERL, int TM>
__global__ void k_gemm(int in1, int in2, int out_id,
                       const float* __restrict__ W1b, const float* __restrict__ W2b,
                       const float* __restrict__ wp, int t, int rows_arg){
  int l  = PERL ? blockIdx.y : 0;
  int nk = PERL ? (l ? 3 : 1) : 1;
  int ks = PERL ? (l ? 1 : 0) : 0;
  int rows = PERL ? NN*nk : rows_arg;
  int rb = blockIdx.x*TM;
  if (rb >= rows) return;
  const float* Wp1 = PERL ? (W1b + l*4096) : W1b;
  const float* Wp2 = DIN ? (PERL ? (W2b + l*4096) : W2b) : (const float*)0;
  __shared__ __align__(16) float As[64][TM+2];
  __shared__ __align__(16) float Ws[64][66];
  int tid = threadIdx.x;
  int tx = tid & 15, ty = tid >> 4;
  const int RT = TM/16;
  u64 acc[RT/2][4];
  #pragma unroll
  for (int i = 0; i < RT/2; i++)
    #pragma unroll
    for (int j = 0; j < 4; j++) acc[i][j] = 0ull;
  const int NP = DIN ? 2 : 1;
  #pragma unroll
  for (int p = 0; p < NP; p++){
    const float* W = (p == 0) ? Wp1 : Wp2;
    #pragma unroll
    for (int ii = 0; ii < TM/4; ii++){
      int idx = ii*256 + tid;
      int rr = idx >> 6, cc = idx & 63;
      int rg = rb + rr;
      float v = 0.f;
      if (rg < rows){
        if (AM == 1 && p == 0){
          const float* M = t ? g_M1 : g_M0;
          int n = rg/nk, k = ks + rg%nk;
          float s0 = M[n*NS4 + cc];
          float P = wp[cc*3+0] + wp[cc*3+1]*s0 + wp[cc*3+2]*s0*s0;
          v = M[(n*4+k)*64 + cc]*P;
        } else if (AM == 3 && p == 0){
          float s0 = g_M1[rg*NS4 + cc];
          v = g_v[cc]*(wp[cc*3+0] + 2.f*wp[cc*3+1]*s0 + 3.f*wp[cc*3+2]*s0*s0);
        } else if (AM == 4 && p == 0){
          float s0 = g_M0[rg*NS4 + cc];
          v = g_gt[rg*64 + cc]*(wp[cc*3+0] + 2.f*wp[cc*3+1]*s0 + 3.f*wp[cc*3+2]*s0*s0);
        } else {
          const float* in = bufsel((DIN && p == 1) ? in2 : in1);
          int adr;
          if (PERL){ int n = rg/nk, k = ks + rg%nk; adr = (n*4+k)*64 + cc; }
          else adr = rg*64 + cc;
          v = in[adr];
        }
      }
      As[cc][rr] = v;
    }
    #pragma unroll
    for (int ii = 0; ii < 16; ii++){
      int idx = ii*256 + tid;
      int rr = idx >> 6, cc = idx & 63;
      if (TR) Ws[cc][rr] = W[idx];
      else    Ws[rr][cc] = W[idx];
    }
    __syncthreads();
    #pragma unroll 4
    for (int kk = 0; kk < 64; kk++){
      const u64* ap = (const u64*)&As[kk][ty*RT];
      const u64* bp = (const u64*)&Ws[kk][tx*4];
      u64 b01 = bp[0], b23 = bp[1];
      u64 B0 = dupf((unsigned)b01), B1 = dupf((unsigned)(b01 >> 32));
      u64 B2 = dupf((unsigned)b23), B3 = dupf((unsigned)(b23 >> 32));
      #pragma unroll
      for (int i = 0; i < RT/2; i++){
        u64 a = ap[i];
        fma2(acc[i][0], a, B0); fma2(acc[i][1], a, B1);
        fma2(acc[i][2], a, B2); fma2(acc[i][3], a, B3);
      }
    }
    __syncthreads();
  }
  float* out = bufsel(out_id);
  #pragma unroll
  for (int i = 0; i < RT/2; i++){
    float2 c0 = asf2(acc[i][0]), c1 = asf2(acc[i][1]);
    float2 c2 = asf2(acc[i][2]), c3 = asf2(acc[i][3]);
    #pragma unroll
    for (int h = 0; h < 2; h++){
      int rg = rb + ty*RT + i*2 + h;
      if (rg >= rows) continue;
      int adr;
      if (PERL){ int n = rg/nk, k = ks + rg%nk; adr = (n*4+k)*64 + tx*4; }
      else adr = rg*64 + tx*4;
      float4 v = h ? make_float4(c0.y, c1.y, c2.y, c3.y)
                   : make_float4(c0.x, c1.x, c2.x, c3.x);
      *(float4*)&out[adr] = v;
    }
  }
}

__global__ void k_agg(int t){
  int node = blockIdx.x*4 + (threadIdx.x >> 6);
  int c = threadIdx.x & 63;
  if (node >= NN) return;
  const float* Fin  = t ? g_F1 : g_F0;
  const float* warr = t ? g_w1 : g_w0;
  float a0 = 0.f, a1 = 0.f, a2 = 0.f, a3 = 0.f;
  int i1 = g_rowr[node+1];
  for (int i = g_rowr[node]; i < i1; i++){
    int e = g_eidr[i];
    int s = g_srcr[i];
    float x = Fin[s*NS4 + c] * warr[e*64 + c];
    float ux = __ldg(&g_uhat[e*3+0]);
    float uy = __ldg(&g_uhat[e*3+1]);
    float uz = __ldg(&g_uhat[e*3+2]);
    a0 += x; a1 += x*ux; a2 += x*uy; a3 += x*uz;
  }
  const float c0 = 0.0625f;
  const float c1 = 0.10825317547305482f;
  g_A[(node*4+0)*64 + c] = a0*c0;
  g_A[(node*4+1)*64 + c] = a1*c1;
  g_A[(node*4+2)*64 + c] = a2*c1;
  g_A[(node*4+3)*64 + c] = a3*c1;
}

__device__ __forceinline__ float blk64_reduce(float v, float* sred, int c){
  sred[c] = v; __syncthreads();
  if (c < 32) sred[c] += sred[c+32];
  __syncthreads();
  float r = 0.f;
  if (c < 32){
    r = sred[c];
    #pragma unroll
    for (int o = 16; o > 0; o >>= 1) r += __shfl_down_sync(0xffffffffu, r, o);
  }
  __syncthreads();
  return r;
}

__global__ void k_ed(int t, const float* __restrict__ we, const float* __restrict__ wd){
  __shared__ float sred[64];
  int n = blockIdx.x, c = threadIdx.x;
  const float* Fn = t ? g_F2 : g_F1;
  float se = blk64_reduce(Fn[n*NS4 + c]*we[c], sred, c);
  if (c == 0) g_en[(1+t)*NN + n] = se;
  #pragma unroll
  for (int m = 0; m < 3; m++){
    float sd = blk64_reduce(Fn[n*NS4 + (1+m)*64 + c]*wd[c], sred, c);
    if (c == 0){
      if (t) g_adip[n*3+m] += sd;
      else   g_adip[n*3+m]  = sd;
    }
  }
}

__global__ void k_gsum(const float* __restrict__ chg, const float* __restrict__ pos,
                       const int* __restrict__ batch){
  __shared__ float bins[96];
  int tid = threadIdx.x;
  if (tid < 96) bins[tid] = 0.f;
  __syncthreads();
  int n = blockIdx.x*256 + tid;
  if (n < NN){
    int g = batch[n];
    atomicAdd(&bins[g*6+0], g_en[n]);
    atomicAdd(&bins[g*6+1], g_en[NN+n]);
    atomicAdd(&bins[g*6+2], g_en[2*NN+n]);
    float q = chg[n];
    #pragma unroll
    for (int j = 0; j < 3; j++)
      atomicAdd(&bins[g*6+3+j], g_adip[n*3+j] + q*pos[n*3+j]);
  }
  __syncthreads();
  if (tid < 96){
    int g = tid/6, j = tid%6;
    float v = bins[tid];
    if (j < 3) atomicAdd(&g_eng[g*3+j], v);
    else       atomicAdd(&g_tdb[g*3+j-3], v);
  }
}

__global__ void k_vec(const float* __restrict__ we1, const float* __restrict__ Wp,
                      const float* __restrict__ Ws){
  int t = threadIdx.x;
  const float* W = (t < 64) ? Wp : Ws;
  int c = t & 63;
  float acc = 0.f;
  #pragma unroll
  for (int d = 0; d < 64; d++) acc += we1[d]*W[c*64+d];
  g_v[t] = acc;
}

__global__ void k_u0(const float* __restrict__ we0, const int* __restrict__ ei){
  int node = blockIdx.x*4 + (threadIdx.x >> 6);
  int c = threadIdx.x & 63;
  if (node >= NN) return;
  float acc = we0[c] + g_v[64+c];
  int i1 = g_rows[node+1];
  for (int i = g_rows[node]; i < i1; i++){
    int e = g_eids[i];
    int r = ei[NE+e];
    acc += g_w1[e*64+c]*g_ga[r*64+c]*0.0625f;
  }
  g_u[node*64 + c] = acc;
}

// backward edge: A = F[s]*gA[r]/16 inline, ga = A@W2^T, epilogue = MLP tail (+forces)
template<int EPI>
__global__ void k_bwd_edge(const float* __restrict__ W2, const float* __restrict__ W1,
                           const int* __restrict__ ei, int t){
  __shared__ __align__(16) float As[64][98];
  __shared__ __align__(16) float Ws[64][66];
  __shared__ float efS[96][9];
  __shared__ float W1s[512];
  __shared__ int sS[96], rS[96];
  int tid = threadIdx.x;
  int rb = blockIdx.x*96;
  for (int i = tid; i < 96; i += 256){
    int rg = rb + i;
    sS[i] = (rg < NE) ? ei[rg] : 0;
    rS[i] = (rg < NE) ? ei[NE+rg] : 0;
  }
  for (int i = tid; i < 768; i += 256){
    int rr = i >> 3, b = i & 7;
    int rg = rb + rr;
    efS[rr][b] = (rg < NE) ? g_ef[rg*8+b] : 0.f;
  }
  for (int i = tid; i < 512; i += 256) W1s[i] = W1[i];
  __syncthreads();
  const float* F = t ? g_F1 : g_F0;
  int ccf = tid & 63;
  #pragma unroll
  for (int ii = 0; ii < 24; ii++){
    int idx = ii*256 + tid;
    int rr = idx >> 6;
    int rg = rb + rr;
    float v = 0.f;
    if (rg < NE) v = F[sS[rr]*NS4 + ccf]*g_ga[rS[rr]*64 + ccf]*0.0625f;
    As[ccf][rr] = v;
  }
  #pragma unroll
  for (int ii = 0; ii < 16; ii++){
    int idx = ii*256 + tid;
    Ws[idx&63][idx>>6] = W2[idx];   // W2^T
  }
  __syncthreads();
  int tx = tid & 15, ty = tid >> 4;
  u64 acc[3][4];
  #pragma unroll
  for (int i = 0; i < 3; i++)
    #pragma unroll
    for (int j = 0; j < 4; j++) acc[i][j] = 0ull;
  #pragma unroll 4
  for (int kk = 0; kk < 64; kk++){
    const u64* ap = (const u64*)&As[kk][ty*6];
    const u64* bp = (const u64*)&Ws[kk][tx*4];
    u64 b01 = bp[0], b23 = bp[1];
    u64 B0 = dupf((unsigned)b01), B1 = dupf((unsigned)(b01 >> 32));
    u64 B2 = dupf((unsigned)b23), B3 = dupf((unsigned)(b23 >> 32));
    #pragma unroll
    for (int i = 0; i < 3; i++){
      u64 a = ap[i];
      fma2(acc[i][0], a, B0); fma2(acc[i][1], a, B1);
      fma2(acc[i][2], a, B2); fma2(acc[i][3], a, B3);
    }
  }
  #pragma unroll
  for (int i2 = 0; i2 < 3; i2++){
    float2 c0 = asf2(acc[i2][0]), c1 = asf2(acc[i2][1]);
    float2 c2 = asf2(acc[i2][2]), c3 = asf2(acc[i2][3]);
    #pragma unroll
    for (int h = 0; h < 2; h++){
      int rloc = ty*6 + i2*2 + h;
      int rg = rb + rloc;
      float gav[4];
      gav[0] = h ? c0.y : c0.x; gav[1] = h ? c1.y : c1.x;
      gav[2] = h ? c2.y : c2.x; gav[3] = h ? c3.y : c3.x;
      float p[8];
      #pragma unroll
      for (int b = 0; b < 8; b++) p[b] = 0.f;
      #pragma unroll
      for (int j = 0; j < 4; j++){
        int cg = tx*4 + j;
        float z = 0.f;
        #pragma unroll
        for (int b = 0; b < 8; b++) z += efS[rloc][b]*W1s[b*64+cg];
        float sig = 1.f/(1.f + expf(-z));
        float gzv = gav[j]*sig*(1.f + z*(1.f - sig));
        #pragma unroll
        for (int b = 0; b < 8; b++) p[b] += gzv*W1s[b*64+cg];
      }
      #pragma unroll
      for (int off = 1; off < 16; off <<= 1)
        #pragma unroll
        for (int b = 0; b < 8; b++) p[b] += __shfl_xor_sync(0xffffffffu, p[b], off);
      if (tx == 0 && rg < NE){
        if (EPI == 1){
          #pragma unroll
          for (int b = 0; b < 8; b++) g_gef[rg*8+b] = p[b];
        } else {
          float gl = 0.f;
          #pragma unroll
          for (int b = 0; b < 8; b++) gl += (g_gef[rg*8+b] + p[b])*g_def[rg*8+b];
          float gx = g_uhat[rg*3+0]*gl;
          float gy = g_uhat[rg*3+1]*gl;
          float gz2 = g_uhat[rg*3+2]*gl;
          int s = sS[rloc], r = rS[rloc];
          atomicAdd(&g_gpos[s*3+0],  gx);
          atomicAdd(&g_gpos[s*3+1],  gy);
          atomicAdd(&g_gpos[s*3+2],  gz2);
          atomicAdd(&g_gpos[r*3+0], -gx);
          atomicAdd(&g_gpos[r*3+1], -gy);
          atomicAdd(&g_gpos[r*3+2], -gz2);
        }
      }
    }
  }
}

__global__ void k_asm_node(float* __restrict__ out){
  int n = blockIdx.x*blockDim.x + threadIdx.x;
  if (n >= NN) return;
  #pragma unroll
  for (int i = 0; i < 3; i++){
    out[64 + n*3 + i] = -g_gpos[n*3+i];
    out[30112 + n*3 + i] = g_adip[n*3+i];
  }
}

__global__ void k_asm_graph(float* __restrict__ out){
  int g = threadIdx.x;
  if (g >= NG) return;
  float c0 = g_eng[g*3+0], c1 = g_eng[g*3+1], c2 = g_eng[g*3+2];
  out[g] = c0 + c1 + c2;
  out[16 + g*3 + 0] = c0;
  out[16 + g*3 + 1] = c1;
  out[16 + g*3 + 2] = c2;
  #pragma unroll
  for (int i = 0; i < 3; i++) out[30064 + g*3 + i] = g_tdb[g*3+i];
}

extern "C" void kernel_launch(void* const* d_in, const int* in_sizes, int n_in,
                              void* d_out, int out_size){
  const float* pos    = (const float*)d_in[0];
  const float* attrs  = (const float*)d_in[1];
  const float* chg    = (const float*)d_in[2];
  const float* shifts = (const float*)d_in[3];
  const float* Wemb   = (const float*)d_in[4];
  const float* ae     = (const float*)d_in[5];
  const float* Wr1    = (const float*)d_in[6];
  const float* Wr2    = (const float*)d_in[7];
  const float* Wmix   = (const float*)d_in[8];
  const float* Wsc    = (const float*)d_in[9];
  const float* wpoly  = (const float*)d_in[10];
  const float* Wprod  = (const float*)d_in[11];
  const float* w_e    = (const float*)d_in[12];
  const float* w_d    = (const float*)d_in[13];
  const int*   ei     = (const int*)d_in[14];
  const int*   batch  = (const int*)d_in[15];
  float* out = (float*)d_out;

  dim3 ggL(469, 2);               // PERL, TM=64 (R5-proven)
  const int ggE = (NE + 95)/96;   // 1667, TM=96 flat
  const int ggS = (NN + 95)/96;   // 105, TM=96 flat

  k_zero<<<(NN*3 + 255)/256, 256>>>();
  k_geom<<<NE/256, 256>>>(pos, shifts, ei);
  k_scan<<<1, 1024>>>();
  k_fill<<<NE/256, 256>>>(ei);
  k_embed<<<(NN*64)/256, 256>>>(attrs, Wemb, ae);

  // forward t=0 (R5-proven path)
  k_mlp1<<<NE/4, 256>>>(Wr1);
  k_gemm<0,false,false,false,96><<<ggE, 256>>>(6, -1, 7, Wr2, 0, 0, 0, NE);
  k_agg<<<NN/4, 256>>>(0);
  k_gemm<0,false,false,true ,64><<<ggL, 256>>>(5, -1, 3, Wmix, 0, 0, 0, 0);
  k_gemm<1,false,true ,true ,64><<<ggL, 256>>>(-1, 0, 1, Wprod, Wsc, wpoly, 0, 0);
  k_ed<<<NN, 64>>>(0, w_e, w_d);

  // forward t=1
  k_mlp1<<<NE/4, 256>>>(Wr1 + 512);
  k_gemm<0,false,false,false,96><<<ggE, 256>>>(6, -1, 8, Wr2 + 4096, 0, 0, 0, NE);
  k_agg<<<NN/4, 256>>>(1);
  k_gemm<0,false,false,true ,64><<<ggL, 256>>>(5, -1, 4, Wmix + 12288, 0, 0, 0, 0);
  k_gemm<1,false,true ,true ,64><<<ggL, 256>>>(-1, 1, 2, Wprod + 12288, Wsc + 12288, wpoly + 192, 1, 0);
  k_ed<<<NN, 64>>>(1, w_e + 64, w_d + 64);
  k_gsum<<<(NN + 255)/256, 256>>>(chg, pos, batch);

  // backward t=1
  k_vec<<<1, 128>>>(w_e + 64, Wprod + 12288, Wsc + 12288);
  k_gemm<3,true ,false,false,96><<<ggS, 256>>>(-1, -1, 11, Wmix + 12288, 0, wpoly + 192, 1, NN);
  k_u0<<<NN/4, 256>>>(w_e, ei);
  k_bwd_edge<1><<<ggE, 256>>>(Wr2 + 4096, Wr1 + 512, ei, 1);

  // backward t=0
  k_gemm<0,true ,false,false,96><<<ggS, 256>>>(9, -1, 10, Wprod, 0, 0, 0, NN);
  k_gemm<4,true ,false,false,96><<<ggS, 256>>>(-1, -1, 11, Wmix, 0, wpoly, 0, NN);
  k_bwd_edge<2><<<ggE, 256>>>(Wr2, Wr1, ei, 0);

  k_asm_node<<<(NN + 255)/256, 256>>>(out);
  k_asm_graph<<<1, 32>>>(out);
}

// round 8
// speedup vs baseline: 2.5407x; 1.1826x over previous
#include <cuda_runtime.h>
#include <math.h>
#include <stdint.h>

#define NN 10000
#define NE 160000
#define ZZ 10
#define NG 16
#define NS4 256
#define RMAXF 5.0f

typedef unsigned long long u64;

__device__ float g_uhat[NE*3];
__device__ float g_len [NE];
__device__ float g_ef  [NE*8];
__device__ float g_def [NE*8];
__device__ float g_w0[NE*64];
__device__ float g_w1[NE*64];
__device__ float g_F0[NN*NS4];
__device__ float g_F1[NN*NS4];
__device__ float g_F2[NN*NS4];
__device__ float g_M0[NN*NS4];
__device__ float g_M1[NN*NS4];
__device__ float g_A [NN*NS4];
__device__ float g_u [NN*64];
__device__ float g_gt[NN*64];
__device__ float g_ga[NN*64];
__device__ float g_v[128];
__device__ float g_gef[NE*8];
__device__ float g_en[3*NN];
__device__ float g_gpos[NN*3];
__device__ float g_adip[NN*3];
__device__ float g_eng[NG*3];
__device__ float g_tdb[NG*3];
__device__ int g_degr[NN], g_degs[NN];
__device__ int g_rowr[NN+1], g_rows[NN+1];
__device__ int g_curr[NN], g_curs[NN];
__device__ int g_eidr[NE], g_eids[NE];
__device__ int g_srcr[NE];

__device__ __forceinline__ float* bufsel(int id){
  switch(id){
    case 0: return g_F0; case 1: return g_F1; case 2: return g_F2;
    case 3: return g_M0; case 4: return g_M1; case 5: return g_A;
    case 7: return g_w0; case 8: return g_w1;
    case 9: return g_u; case 10: return g_gt; default: return g_ga;
  }
}

__device__ __forceinline__ u64 dupf(unsigned x){
  u64 r; asm("mov.b64 %0,{%1,%1};" : "=l"(r) : "r"(x)); return r;
}
__device__ __forceinline__ void fma2(u64 &c, u64 a, u64 b){
  asm("fma.rn.f32x2 %0,%1,%2,%3;" : "=l"(c) : "l"(a), "l"(b), "l"(c));
}
__device__ __forceinline__ float2 asf2(u64 v){
  float2 f;
  f.x = __uint_as_float((unsigned)v);
  f.y = __uint_as_float((unsigned)(v >> 32));
  return f;
}

__global__ void k_zero(){
  int i = blockIdx.x*blockDim.x + threadIdx.x;
  if (i < NN*3) g_gpos[i] = 0.f;
  if (i < NG*3) { g_eng[i] = 0.f; g_tdb[i] = 0.f; }
  if (i < NN)   { g_degr[i] = 0; g_degs[i] = 0; }
}

__global__ void k_geom(const float* __restrict__ pos, const float* __restrict__ shifts,
                       const int* __restrict__ ei){
  int e = blockIdx.x*blockDim.x + threadIdx.x;
  if (e >= NE) return;
  int s = ei[e], r = ei[NE+e];
  atomicAdd(&g_degs[s], 1);
  atomicAdd(&g_degr[r], 1);
  float vx = pos[s*3+0] - pos[r*3+0] + shifts[e*3+0];
  float vy = pos[s*3+1] - pos[r*3+1] + shifts[e*3+1];
  float vz = pos[s*3+2] - pos[r*3+2] + shifts[e*3+2];
  float len = sqrtf(vx*vx + vy*vy + vz*vz + 1e-12f);
  float inv = 1.f/len;
  g_uhat[e*3+0] = vx*inv; g_uhat[e*3+1] = vy*inv; g_uhat[e*3+2] = vz*inv;
  g_len[e] = len;
  float u = len / RMAXF;
  float fc = 0.f, dfc = 0.f;
  if (u < 1.f){
    float u2 = u*u, u4 = u2*u2, u5 = u4*u, u6 = u5*u, u7 = u6*u;
    fc  = 1.f - 21.f*u5 + 35.f*u6 - 15.f*u7;
    dfc = (-105.f*u4 + 210.f*u5 - 105.f*u6) / RMAXF;
  }
  float ire = 1.f/(len + 1e-9f);
  const float amp = 0.6324555320336759f;
  const float PIC = 3.14159265358979323846f;
  float th = PIC*len/RMAXF;
  float s1, c1;
  sincosf(th, &s1, &c1);
  float twoc = 2.f*c1;
  float sp = 0.f, cp = 1.f, sc = s1, cc = c1;
  #pragma unroll
  for (int b = 0; b < 8; b++){
    float kb = (float)(b+1)*PIC/RMAXF;
    float bess  = amp*sc*ire;
    float dbess = amp*(kb*cc*ire - sc*ire*ire);
    g_ef [e*8+b] = bess*fc;
    g_def[e*8+b] = dbess*fc + bess*dfc;
    float sn = twoc*sc - sp, cn = twoc*cc - cp;
    sp = sc; cp = cc; sc = sn; cc = cn;
  }
}

__global__ void k_scan(){
  __shared__ int sh[1024];
  int t = threadIdx.x;
  for (int pass = 0; pass < 2; pass++){
    int* deg = pass ? g_degs : g_degr;
    int* row = pass ? g_rows : g_rowr;
    int* cur = pass ? g_curs : g_curr;
    int base = t*10;
    int s = 0;
    for (int j = 0; j < 10; j++){ int n = base+j; if (n < NN) s += deg[n]; }
    sh[t] = s; __syncthreads();
    for (int off = 1; off < 1024; off <<= 1){
      int v = (t >= off) ? sh[t-off] : 0;
      __syncthreads();
      sh[t] += v;
      __syncthreads();
    }
    int run = sh[t] - s;
    for (int j = 0; j < 10; j++){
      int n = base+j;
      if (n < NN){ row[n] = run; cur[n] = run; run += deg[n]; }
    }
    if (t == 1023) row[NN] = sh[1023];
    __syncthreads();
  }
}

__global__ void k_fill(const int* __restrict__ ei){
  int e = blockIdx.x*blockDim.x + threadIdx.x;
  if (e >= NE) return;
  int s = ei[e], r = ei[NE+e];
  int p = atomicAdd(&g_curs[s], 1); g_eids[p] = e;
  int q = atomicAdd(&g_curr[r], 1); g_eidr[q] = e; g_srcr[q] = s;
}

__global__ void k_embed(const float* __restrict__ attrs, const float* __restrict__ Wemb,
                        const float* __restrict__ ae){
  int i = blockIdx.x*blockDim.x + threadIdx.x;
  if (i >= NN*64) return;
  int n = i >> 6, c = i & 63;
  float acc = 0.f;
  #pragma unroll
  for (int zq = 0; zq < ZZ; zq++) acc += attrs[n*ZZ+zq]*Wemb[zq*64+c];
  g_F0[n*NS4 + c] = acc;
  #pragma unroll
  for (int k = 1; k < 4; k++) g_F0[n*NS4 + k*64 + c] = 0.f;
  if (c == 0){
    float e0 = 0.f;
    #pragma unroll
    for (int zq = 0; zq < ZZ; zq++) e0 += attrs[n*ZZ+zq]*ae[zq];
    g_en[n] = e0;
  }
}

// fused: w = silu(ef@W1)@W2, act computed in the A-tile load; output chosen by id
__global__ void k_fwd_edge(const float* __restrict__ W1, const float* __restrict__ W2,
                           int out_id){
  __shared__ __align__(16) float As[64][98];
  __shared__ __align__(16) float Ws[64][66];
  __shared__ float efS[96][9];
  int tid = threadIdx.x;
  int rb = blockIdx.x*96;
  for (int i = tid; i < 768; i += 256){
    int rr = i >> 3, b = i & 7;
    int rg = rb + rr;
    efS[rr][b] = (rg < NE) ? g_ef[rg*8+b] : 0.f;
  }
  float w1c[8];
  int ccf = tid & 63;
  #pragma unroll
  for (int b = 0; b < 8; b++) w1c[b] = W1[b*64 + ccf];
  __syncthreads();
  #pragma unroll
  for (int ii = 0; ii < 24; ii++){
    int idx = ii*256 + tid;
    int rr = idx >> 6;
    int rg = rb + rr;
    float v = 0.f;
    if (rg < NE){
      float z = 0.f;
      #pragma unroll
      for (int b = 0; b < 8; b++) z += efS[rr][b]*w1c[b];
      float sig = 1.f/(1.f + expf(-z));
      v = z*sig;
    }
    As[ccf][rr] = v;
  }
  #pragma unroll
  for (int ii = 0; ii < 16; ii++){
    int idx = ii*256 + tid;
    Ws[idx>>6][idx&63] = W2[idx];
  }
  __syncthreads();
  int tx = tid & 15, ty = tid >> 4;
  u64 acc[3][4];
  #pragma unroll
  for (int i = 0; i < 3; i++)
    #pragma unroll
    for (int j = 0; j < 4; j++) acc[i][j] = 0ull;
  #pragma unroll 4
  for (int kk = 0; kk < 64; kk++){
    const u64* ap = (const u64*)&As[kk][ty*6];
    const u64* bp = (const u64*)&Ws[kk][tx*4];
    u64 b01 = bp[0], b23 = bp[1];
    u64 B0 = dupf((unsigned)b01), B1 = dupf((unsigned)(b01 >> 32));
    u64 B2 = dupf((unsigned)b23), B3 = dupf((unsigned)(b23 >> 32));
    #pragma unroll
    for (int i = 0; i < 3; i++){
      u64 a = ap[i];
      fma2(acc[i][0], a, B0); fma2(acc[i][1], a, B1);
      fma2(acc[i][2], a, B2); fma2(acc[i][3], a, B3);
    }
  }
  float* out = bufsel(out_id);
  #pragma unroll
  for (int i = 0; i < 3; i++){
    float2 c0 = asf2(acc[i][0]), c1 = asf2(acc[i][1]);
    float2 c2 = asf2(acc[i][2]), c3 = asf2(acc[i][3]);
    #pragma unroll
    for (int h = 0; h < 2; h++){
      int rg = rb + ty*6 + i*2 + h;
      if (rg >= NE) continue;
      float4 v = h ? make_float4(c0.y, c1.y, c2.y, c3.y)
                   : make_float4(c0.x, c1.x, c2.x, c3.x);
      *(float4*)&out[rg*64 + tx*4] = v;
    }
  }
}

// AM: 0 plain, 1 poly-fwd (DIN p0 from M), 3 gM1-from-g_v, 4 gM0-from-gt
template<int AM, bool TR, bool DIN, bool PERL, int TM>
__global__ void k_gemm(int in1, int in2, int out_id,
                       const float* __restrict__ W1b, const float* __restrict__ W2b,
                       const float* __restrict__ wp, int t, int rows_arg){
  int l  = PERL ? blockIdx.y : 0;
  int nk = PERL ? (l ? 3 : 1) : 1;
  int ks = PERL ? (l ? 1 : 0) : 0;
  int rows = PERL ? NN*nk : rows_arg;
  int rb = blockIdx.x*TM;
  if (rb >= rows) return;
  const float* Wp1 = PERL ? (W1b + l*4096) : W1b;
  const float* Wp2 = DIN ? (PERL ? (W2b + l*4096) : W2b) : (const float*)0;
  __shared__ __align__(16) float As[64][TM+2];
  __shared__ __align__(16) float Ws[64][66];
  int tid = threadIdx.x;
  int tx = tid & 15, ty = tid >> 4;
  const int RT = TM/16;
  u64 acc[RT/2][4];
  #pragma unroll
  for (int i = 0; i < RT/2; i++)
    #pragma unroll
    for (int j = 0; j < 4; j++) acc[i][j] = 0ull;
  const int NP = DIN ? 2 : 1;
  #pragma unroll
  for (int p = 0; p < NP; p++){
    const float* W = (p == 0) ? Wp1 : Wp2;
    #pragma unroll
    for (int ii = 0; ii < TM/4; ii++){
      int idx = ii*256 + tid;
      int rr = idx >> 6, cc = idx & 63;
      int rg = rb + rr;
      float v = 0.f;
      if (rg < rows){
        if (AM == 1 && p == 0){
          const float* M = t ? g_M1 : g_M0;
          int n = rg/nk, k = ks + rg%nk;
          float s0 = M[n*NS4 + cc];
          float P = wp[cc*3+0] + wp[cc*3+1]*s0 + wp[cc*3+2]*s0*s0;
          v = M[(n*4+k)*64 + cc]*P;
        } else if (AM == 3 && p == 0){
          float s0 = g_M1[rg*NS4 + cc];
          v = g_v[cc]*(wp[cc*3+0] + 2.f*wp[cc*3+1]*s0 + 3.f*wp[cc*3+2]*s0*s0);
        } else if (AM == 4 && p == 0){
          float s0 = g_M0[rg*NS4 + cc];
          v = g_gt[rg*64 + cc]*(wp[cc*3+0] + 2.f*wp[cc*3+1]*s0 + 3.f*wp[cc*3+2]*s0*s0);
        } else {
          const float* in = bufsel((DIN && p == 1) ? in2 : in1);
          int adr;
          if (PERL){ int n = rg/nk, k = ks + rg%nk; adr = (n*4+k)*64 + cc; }
          else adr = rg*64 + cc;
          v = in[adr];
        }
      }
      As[cc][rr] = v;
    }
    #pragma unroll
    for (int ii = 0; ii < 16; ii++){
      int idx = ii*256 + tid;
      int rr = idx >> 6, cc = idx & 63;
      if (TR) Ws[cc][rr] = W[idx];
      else    Ws[rr][cc] = W[idx];
    }
    __syncthreads();
    #pragma unroll 4
    for (int kk = 0; kk < 64; kk++){
      const u64* ap = (const u64*)&As[kk][ty*RT];
      const u64* bp = (const u64*)&Ws[kk][tx*4];
      u64 b01 = bp[0], b23 = bp[1];
      u64 B0 = dupf((unsigned)b01), B1 = dupf((unsigned)(b01 >> 32));
      u64 B2 = dupf((unsigned)b23), B3 = dupf((unsigned)(b23 >> 32));
      #pragma unroll
      for (int i = 0; i < RT/2; i++){
        u64 a = ap[i];
        fma2(acc[i][0], a, B0); fma2(acc[i][1], a, B1);
        fma2(acc[i][2], a, B2); fma2(acc[i][3], a, B3);
      }
    }
    __syncthreads();
  }
  float* out = bufsel(out_id);
  #pragma unroll
  for (int i = 0; i < RT/2; i++){
    float2 c0 = asf2(acc[i][0]), c1 = asf2(acc[i][1]);
    float2 c2 = asf2(acc[i][2]), c3 = asf2(acc[i][3]);
    #pragma unroll
    for (int h = 0; h < 2; h++){
      int rg = rb + ty*RT + i*2 + h;
      if (rg >= rows) continue;
      int adr;
      if (PERL){ int n = rg/nk, k = ks + rg%nk; adr = (n*4+k)*64 + tx*4; }
      else adr = rg*64 + tx*4;
      float4 v = h ? make_float4(c0.y, c1.y, c2.y, c3.y)
                   : make_float4(c0.x, c1.x, c2.x, c3.x);
      *(float4*)&out[adr] = v;
    }
  }
}

__global__ void k_agg(int t){
  int node = blockIdx.x*4 + (threadIdx.x >> 6);
  int c = threadIdx.x & 63;
  if (node >= NN) return;
  const float* Fin  = t ? g_F1 : g_F0;
  const float* warr = t ? g_w1 : g_w0;
  float a0 = 0.f, a1 = 0.f, a2 = 0.f, a3 = 0.f;
  int i1 = g_rowr[node+1];
  for (int i = g_rowr[node]; i < i1; i++){
    int e = g_eidr[i];
    int s = g_srcr[i];
    float x = Fin[s*NS4 + c] * warr[e*64 + c];
    float ux = __ldg(&g_uhat[e*3+0]);
    float uy = __ldg(&g_uhat[e*3+1]);
    float uz = __ldg(&g_uhat[e*3+2]);
    a0 += x; a1 += x*ux; a2 += x*uy; a3 += x*uz;
  }
  const float c0 = 0.0625f;
  const float c1 = 0.10825317547305482f;
  g_A[(node*4+0)*64 + c] = a0*c0;
  g_A[(node*4+1)*64 + c] = a1*c1;
  g_A[(node*4+2)*64 + c] = a2*c1;
  g_A[(node*4+3)*64 + c] = a3*c1;
}

// warp-per-node energy + dipole
__global__ void k_ed(int t, const float* __restrict__ we, const float* __restrict__ wd){
  int node = blockIdx.x*8 + (threadIdx.x >> 5);
  int lane = threadIdx.x & 31;
  if (node >= NN) return;
  const float* Fn = t ? g_F2 : g_F1;
  int c0 = lane, c1 = lane + 32;
  float v0 = Fn[node*NS4 + c0]*we[c0] + Fn[node*NS4 + c1]*we[c1];
  float v1 = Fn[node*NS4 + 64 + c0]*wd[c0] + Fn[node*NS4 + 64 + c1]*wd[c1];
  float v2 = Fn[node*NS4 + 128 + c0]*wd[c0] + Fn[node*NS4 + 128 + c1]*wd[c1];
  float v3 = Fn[node*NS4 + 192 + c0]*wd[c0] + Fn[node*NS4 + 192 + c1]*wd[c1];
  #pragma unroll
  for (int o = 16; o > 0; o >>= 1){
    v0 += __shfl_down_sync(0xffffffffu, v0, o);
    v1 += __shfl_down_sync(0xffffffffu, v1, o);
    v2 += __shfl_down_sync(0xffffffffu, v2, o);
    v3 += __shfl_down_sync(0xffffffffu, v3, o);
  }
  if (lane == 0){
    g_en[(1+t)*NN + node] = v0;
    if (t){
      g_adip[node*3+0] += v1; g_adip[node*3+1] += v2; g_adip[node*3+2] += v3;
    } else {
      g_adip[node*3+0]  = v1; g_adip[node*3+1]  = v2; g_adip[node*3+2]  = v3;
    }
  }
}

__global__ void k_gsum(const float* __restrict__ chg, const float* __restrict__ pos,
                       const int* __restrict__ batch){
  __shared__ float bins[96];
  int tid = threadIdx.x;
  if (tid < 96) bins[tid] = 0.f;
  __syncthreads();
  int n = blockIdx.x*256 + tid;
  if (n < NN){
    int g = batch[n];
    atomicAdd(&bins[g*6+0], g_en[n]);
    atomicAdd(&bins[g*6+1], g_en[NN+n]);
    atomicAdd(&bins[g*6+2], g_en[2*NN+n]);
    float q = chg[n];
    #pragma unroll
    for (int j = 0; j < 3; j++)
      atomicAdd(&bins[g*6+3+j], g_adip[n*3+j] + q*pos[n*3+j]);
  }
  __syncthreads();
  if (tid < 96){
    int g = tid/6, j = tid%6;
    float v = bins[tid];
    if (j < 3) atomicAdd(&g_eng[g*3+j], v);
    else       atomicAdd(&g_tdb[g*3+j-3], v);
  }
}

__global__ void k_vec(const float* __restrict__ we1, const float* __restrict__ Wp,
                      const float* __restrict__ Ws){
  int t = threadIdx.x;
  const float* W = (t < 64) ? Wp : Ws;
  int c = t & 63;
  float acc = 0.f;
  #pragma unroll
  for (int d = 0; d < 64; d++) acc += we1[d]*W[c*64+d];
  g_v[t] = acc;
}

__global__ void k_u0(const float* __restrict__ we0, const int* __restrict__ ei){
  int node = blockIdx.x*4 + (threadIdx.x >> 6);
  int c = threadIdx.x & 63;
  if (node >= NN) return;
  float acc = we0[c] + g_v[64+c];
  int i1 = g_rows[node+1];
  for (int i = g_rows[node]; i < i1; i++){
    int e = g_eids[i];
    int r = ei[NE+e];
    acc += g_w1[e*64+c]*g_ga[r*64+c]*0.0625f;
  }
  g_u[node*64 + c] = acc;
}

// backward edge: A = F[s]*gA[r]/16 inline, ga = A@W2^T, epilogue = MLP tail (+forces)
template<int EPI>
__global__ void k_bwd_edge(const float* __restrict__ W2, const float* __restrict__ W1,
                           const int* __restrict__ ei, int t){
  __shared__ __align__(16) float As[64][98];
  __shared__ __align__(16) float Ws[64][66];
  __shared__ float efS[96][9];
  __shared__ float W1s[512];
  __shared__ int sS[96], rS[96];
  int tid = threadIdx.x;
  int rb = blockIdx.x*96;
  for (int i = tid; i < 96; i += 256){
    int rg = rb + i;
    sS[i] = (rg < NE) ? ei[rg] : 0;
    rS[i] = (rg < NE) ? ei[NE+rg] : 0;
  }
  for (int i = tid; i < 768; i += 256){
    int rr = i >> 3, b = i & 7;
    int rg = rb + rr;
    efS[rr][b] = (rg < NE) ? g_ef[rg*8+b] : 0.f;
  }
  for (int i = tid; i < 512; i += 256) W1s[i] = W1[i];
  __syncthreads();
  const float* F = t ? g_F1 : g_F0;
  int ccf = tid & 63;
  #pragma unroll
  for (int ii = 0; ii < 24; ii++){
    int idx = ii*256 + tid;
    int rr = idx >> 6;
    int rg = rb + rr;
    float v = 0.f;
    if (rg < NE) v = F[sS[rr]*NS4 + ccf]*g_ga[rS[rr]*64 + ccf]*0.0625f;
    As[ccf][rr] = v;
  }
  #pragma unroll
  for (int ii = 0; ii < 16; ii++){
    int idx = ii*256 + tid;
    Ws[idx&63][idx>>6] = W2[idx];   // W2^T
  }
  __syncthreads();
  int tx = tid & 15, ty = tid >> 4;
  u64 acc[3][4];
  #pragma unroll
  for (int i = 0; i < 3; i++)
    #pragma unroll
    for (int j = 0; j < 4; j++) acc[i][j] = 0ull;
  #pragma unroll 4
  for (int kk = 0; kk < 64; kk++){
    const u64* ap = (const u64*)&As[kk][ty*6];
    const u64* bp = (const u64*)&Ws[kk][tx*4];
    u64 b01 = bp[0], b23 = bp[1];
    u64 B0 = dupf((unsigned)b01), B1 = dupf((unsigned)(b01 >> 32));
    u64 B2 = dupf((unsigned)b23), B3 = dupf((unsigned)(b23 >> 32));
    #pragma unroll
    for (int i = 0; i < 3; i++){
      u64 a = ap[i];
      fma2(acc[i][0], a, B0); fma2(acc[i][1], a, B1);
      fma2(acc[i][2], a, B2); fma2(acc[i][3], a, B3);
    }
  }
  #pragma unroll
  for (int i2 = 0; i2 < 3; i2++){
    float2 c0 = asf2(acc[i2][0]), c1 = asf2(acc[i2][1]);
    float2 c2 = asf2(acc[i2][2]), c3 = asf2(acc[i2][3]);
    #pragma unroll
    for (int h = 0; h < 2; h++){
      int rloc = ty*6 + i2*2 + h;
      int rg = rb + rloc;
      float gav[4];
      gav[0] = h ? c0.y : c0.x; gav[1] = h ? c1.y : c1.x;
      gav[2] = h ? c2.y : c2.x; gav[3] = h ? c3.y : c3.x;
      float p[8];
      #pragma unroll
      for (int b = 0; b < 8; b++) p[b] = 0.f;
      #pragma unroll
      for (int j = 0; j < 4; j++){
        int cg = tx*4 + j;
        float z = 0.f;
        #pragma unroll
        for (int b = 0; b < 8; b++) z += efS[rloc][b]*W1s[b*64+cg];
        float sig = 1.f/(1.f + expf(-z));
        float gzv = gav[j]*sig*(1.f + z*(1.f - sig));
        #pragma unroll
        for (int b = 0; b < 8; b++) p[b] += gzv*W1s[b*64+cg];
      }
      #pragma unroll
      for (int off = 1; off < 16; off <<= 1)
        #pragma unroll
        for (int b = 0; b < 8; b++) p[b] += __shfl_xor_sync(0xffffffffu, p[b], off);
      if (tx == 0 && rg < NE){
        if (EPI == 1){
          #pragma unroll
          for (int b = 0; b < 8; b++) g_gef[rg*8+b] = p[b];
        } else {
          float gl = 0.f;
          #pragma unroll
          for (int b = 0; b < 8; b++) gl += (g_gef[rg*8+b] + p[b])*g_def[rg*8+b];
          float gx = g_uhat[rg*3+0]*gl;
          float gy = g_uhat[rg*3+1]*gl;
          float gz2 = g_uhat[rg*3+2]*gl;
          int s = sS[rloc], r = rS[rloc];
          atomicAdd(&g_gpos[s*3+0],  gx);
          atomicAdd(&g_gpos[s*3+1],  gy);
          atomicAdd(&g_gpos[s*3+2],  gz2);
          atomicAdd(&g_gpos[r*3+0], -gx);
          atomicAdd(&g_gpos[r*3+1], -gy);
          atomicAdd(&g_gpos[r*3+2], -gz2);
        }
      }
    }
  }
}

__global__ void k_asm_node(float* __restrict__ out){
  int n = blockIdx.x*blockDim.x + threadIdx.x;
  if (n >= NN) return;
  #pragma unroll
  for (int i = 0; i < 3; i++){
    out[64 + n*3 + i] = -g_gpos[n*3+i];
    out[30112 + n*3 + i] = g_adip[n*3+i];
  }
}

__global__ void k_asm_graph(float* __restrict__ out){
  int g = threadIdx.x;
  if (g >= NG) return;
  float c0 = g_eng[g*3+0], c1 = g_eng[g*3+1], c2 = g_eng[g*3+2];
  out[g] = c0 + c1 + c2;
  out[16 + g*3 + 0] = c0;
  out[16 + g*3 + 1] = c1;
  out[16 + g*3 + 2] = c2;
  #pragma unroll
  for (int i = 0; i < 3; i++) out[30064 + g*3 + i] = g_tdb[g*3+i];
}

extern "C" void kernel_launch(void* const* d_in, const int* in_sizes, int n_in,
                              void* d_out, int out_size){
  const float* pos    = (const float*)d_in[0];
  const float* attrs  = (const float*)d_in[1];
  const float* chg    = (const float*)d_in[2];
  const float* shifts = (const float*)d_in[3];
  const float* Wemb   = (const float*)d_in[4];
  const float* ae     = (const float*)d_in[5];
  const float* Wr1    = (const float*)d_in[6];
  const float* Wr2    = (const float*)d_in[7];
  const float* Wmix   = (const float*)d_in[8];
  const float* Wsc    = (const float*)d_in[9];
  const float* wpoly  = (const float*)d_in[10];
  const float* Wprod  = (const float*)d_in[11];
  const float* w_e    = (const float*)d_in[12];
  const float* w_d    = (const float*)d_in[13];
  const int*   ei     = (const int*)d_in[14];
  const int*   batch  = (const int*)d_in[15];
  float* out = (float*)d_out;

  dim3 ggL(469, 2);
  const int ggE = (NE + 95)/96;
  const int ggS = (NN + 95)/96;

  k_zero<<<(NN*3 + 255)/256, 256>>>();
  k_geom<<<NE/256, 256>>>(pos, shifts, ei);
  k_scan<<<1, 1024>>>();
  k_fill<<<NE/256, 256>>>(ei);
  k_embed<<<(NN*64)/256, 256>>>(attrs, Wemb, ae);

  // forward t=0
  k_fwd_edge<<<ggE, 256>>>(Wr1, Wr2, 7);
  k_agg<<<NN/4, 256>>>(0);
  k_gemm<0,false,false,true ,64><<<ggL, 256>>>(5, -1, 3, Wmix, 0, 0, 0, 0);
  k_gemm<1,false,true ,true ,64><<<ggL, 256>>>(-1, 0, 1, Wprod, Wsc, wpoly, 0, 0);
  k_ed<<<NN/8, 256>>>(0, w_e, w_d);

  // forward t=1
  k_fwd_edge<<<ggE, 256>>>(Wr1 + 512, Wr2 + 4096, 8);
  k_agg<<<NN/4, 256>>>(1);
  k_gemm<0,false,false,true ,64><<<ggL, 256>>>(5, -1, 4, Wmix + 12288, 0, 0, 0, 0);
  k_gemm<1,false,true ,true ,64><<<ggL, 256>>>(-1, 1, 2, Wprod + 12288, Wsc + 12288, wpoly + 192, 1, 0);
  k_ed<<<NN/8, 256>>>(1, w_e + 64, w_d + 64);
  k_gsum<<<(NN + 255)/256, 256>>>(chg, pos, batch);

  // backward t=1
  k_vec<<<1, 128>>>(w_e + 64, Wprod + 12288, Wsc + 12288);
  k_gemm<3,true ,false,false,96><<<ggS, 256>>>(-1, -1, 11, Wmix + 12288, 0, wpoly + 192, 1, NN);
  k_u0<<<NN/4, 256>>>(w_e, ei);
  k_bwd_edge<1><<<ggE, 256>>>(Wr2 + 4096, Wr1 + 512, ei, 1);

  // backward t=0
  k_gemm<0,true ,false,false,96><<<ggS, 256>>>(9, -1, 10, Wprod, 0, 0, 0, NN);
  k_gemm<4,true ,false,false,96><<<ggS, 256>>>(-1, -1, 11, Wmix, 0, wpoly, 0, NN);
  k_bwd_edge<2><<<ggE, 256>>>(Wr2, Wr1, ei, 0);

  k_asm_node<<<(NN + 255)/256, 256>>>(out);
  k_asm_graph<<<1, 32>>>(out);
}